// round 1
// baseline (speedup 1.0000x reference)
#include <cuda_runtime.h>
#include <cstdint>

#define HIDDEN 3072
#define NHEADS 24
#define HDIM   128
#define MLPH   12288
#define LSEQ   2048
#define N1     21504   // 3*HIDDEN + MLPH
#define NCAT   15360   // HIDDEN + MLPH
#define NMOD   9216

// ---------------- scratch (static device globals; no allocs) ----------------
__device__ float g_mod[NMOD];
__device__ float g_xmod[LSEQ * HIDDEN];
__device__ float g_h[LSEQ * N1];
__device__ float g_q[LSEQ * HIDDEN];
__device__ float g_k[LSEQ * HIDDEN];
__device__ float g_a2[LSEQ * NCAT];

// ---------------- helpers ----------------
__device__ __forceinline__ uint32_t f2tf32(float f) {
    uint32_t u;
    asm("cvt.rna.tf32.f32 %0, %1;" : "=r"(u) : "f"(f));
    return u;
}

__device__ __forceinline__ void mma8(float* d, const uint32_t* a, const uint32_t* b) {
    asm volatile(
        "mma.sync.aligned.m16n8k8.row.col.f32.tf32.tf32.f32 "
        "{%0,%1,%2,%3}, {%4,%5,%6,%7}, {%8,%9}, {%0,%1,%2,%3};"
        : "+f"(d[0]), "+f"(d[1]), "+f"(d[2]), "+f"(d[3])
        : "r"(a[0]), "r"(a[1]), "r"(a[2]), "r"(a[3]), "r"(b[0]), "r"(b[1]));
}

__device__ __forceinline__ float gelu1(float x) {
    float x3 = x * x * x;
    return 0.5f * x * (1.f + tanhf(0.7978845608028654f * (x + 0.044715f * x3)));
}

// ---------------- 1) mod = silu(vec) @ mod_w + mod_b ----------------
__global__ void __launch_bounds__(256) k_mod(const float* __restrict__ vec,
                                             const float* __restrict__ W,
                                             const float* __restrict__ b) {
    __shared__ float sm[HIDDEN];
    for (int i = threadIdx.x; i < HIDDEN; i += 256) {
        float v = vec[i];
        sm[i] = v / (1.f + expf(-v));
    }
    __syncthreads();
    int j = blockIdx.x * 256 + threadIdx.x;  // j < 9216
    float s0 = 0.f, s1 = 0.f, s2 = 0.f, s3 = 0.f;
    #pragma unroll 4
    for (int k = 0; k < HIDDEN; k += 4) {
        s0 = fmaf(sm[k + 0], W[(size_t)(k + 0) * NMOD + j], s0);
        s1 = fmaf(sm[k + 1], W[(size_t)(k + 1) * NMOD + j], s1);
        s2 = fmaf(sm[k + 2], W[(size_t)(k + 2) * NMOD + j], s2);
        s3 = fmaf(sm[k + 3], W[(size_t)(k + 3) * NMOD + j], s3);
    }
    g_mod[j] = (s0 + s1) + (s2 + s3) + b[j];
}

// ---------------- 2) x_mod = (1+scale)*LN(x) + shift ----------------
__global__ void __launch_bounds__(256) k_ln(const float* __restrict__ x) {
    int row = blockIdx.x;
    int tid = threadIdx.x;
    const float* xr = x + (size_t)row * HIDDEN;
    float s = 0.f, s2 = 0.f;
    for (int i = tid; i < HIDDEN; i += 256) {
        float v = xr[i];
        s += v;
        s2 = fmaf(v, v, s2);
    }
    __shared__ float rs[8], rs2[8];
    for (int o = 16; o; o >>= 1) {
        s  += __shfl_xor_sync(~0u, s, o);
        s2 += __shfl_xor_sync(~0u, s2, o);
    }
    if ((tid & 31) == 0) { rs[tid >> 5] = s; rs2[tid >> 5] = s2; }
    __syncthreads();
    float ts = 0.f, ts2 = 0.f;
    #pragma unroll
    for (int i = 0; i < 8; i++) { ts += rs[i]; ts2 += rs2[i]; }
    float mu  = ts * (1.f / HIDDEN);
    float var = ts2 * (1.f / HIDDEN) - mu * mu;
    float rstd = rsqrtf(var + 1e-6f);
    float* o = g_xmod + (size_t)row * HIDDEN;
    for (int i = tid; i < HIDDEN; i += 256) {
        float v = (xr[i] - mu) * rstd;
        o[i] = fmaf(g_mod[HIDDEN + i], v, v + g_mod[i]);  // (1+scale)*v + shift
    }
}

// ---------------- 3/7) tf32 GEMM: MODE 0: g_h = g_xmod@w1+b1 ; MODE 1: out = x + gate*(g_a2@w2+b2)
template <int MODE>
__global__ void __launch_bounds__(256) gemm_tf32(const float* __restrict__ B,
                                                 const float* __restrict__ bias,
                                                 float* __restrict__ Cout,
                                                 const float* __restrict__ xres) {
    constexpr int K = (MODE == 0) ? HIDDEN : NCAT;
    constexpr int N = (MODE == 0) ? N1 : HIDDEN;
    constexpr int AS = 20;    // BK(16)+4 stride
    constexpr int BS = 136;   // BN(128)+8 stride

    __shared__ uint32_t As[2][128 * AS];
    __shared__ uint32_t Bs[2][16 * BS];

    const float* A = (MODE == 0) ? g_xmod : g_a2;
    float* C = (MODE == 0) ? g_h : Cout;

    int tid = threadIdx.x;
    int bm = blockIdx.y, bn = blockIdx.x;
    int warp = tid >> 5, lane = tid & 31;
    int wm = warp & 3, wn = warp >> 2;
    int g = lane >> 2, tg = lane & 3;

    int ar = tid >> 2;          // A load row (0..63, +64)
    int ac = (tid & 3) << 2;    // A load col (0,4,8,12)
    int br = tid >> 5;          // B load row (0..7, +8)
    int bc = (tid & 31) << 2;   // B load col

    const float* Aptr = A + (size_t)(bm * 128) * K;
    const float* Bptr = B + bn * 128;

    float acc[2][8][4];
    #pragma unroll
    for (int i = 0; i < 2; i++)
        #pragma unroll
        for (int j = 0; j < 8; j++)
            #pragma unroll
            for (int v = 0; v < 4; v++) acc[i][j][v] = 0.f;

    float4 av0, av1, bv0, bv1;
    auto loadg = [&](int k0) {
        av0 = *(const float4*)(Aptr + (size_t)ar * K + k0 + ac);
        av1 = *(const float4*)(Aptr + (size_t)(ar + 64) * K + k0 + ac);
        bv0 = *(const float4*)(Bptr + (size_t)(k0 + br) * N + bc);
        bv1 = *(const float4*)(Bptr + (size_t)(k0 + br + 8) * N + bc);
    };
    auto stores = [&](int buf) {
        *(uint4*)&As[buf][ar * AS + ac] =
            make_uint4(f2tf32(av0.x), f2tf32(av0.y), f2tf32(av0.z), f2tf32(av0.w));
        *(uint4*)&As[buf][(ar + 64) * AS + ac] =
            make_uint4(f2tf32(av1.x), f2tf32(av1.y), f2tf32(av1.z), f2tf32(av1.w));
        *(uint4*)&Bs[buf][br * BS + bc] =
            make_uint4(f2tf32(bv0.x), f2tf32(bv0.y), f2tf32(bv0.z), f2tf32(bv0.w));
        *(uint4*)&Bs[buf][(br + 8) * BS + bc] =
            make_uint4(f2tf32(bv1.x), f2tf32(bv1.y), f2tf32(bv1.z), f2tf32(bv1.w));
    };

    loadg(0);
    stores(0);
    __syncthreads();

    int buf = 0;
    const int Kt = K / 16;
    for (int kt = 1; kt <= Kt; kt++) {
        if (kt < Kt) loadg(kt * 16);
        #pragma unroll
        for (int kk = 0; kk < 2; kk++) {
            int k = kk * 8;
            uint32_t af[2][4];
            uint32_t bfr[8][2];
            #pragma unroll
            for (int i = 0; i < 2; i++) {
                int r = wm * 32 + i * 16 + g;
                af[i][0] = As[buf][r * AS + k + tg];
                af[i][1] = As[buf][(r + 8) * AS + k + tg];
                af[i][2] = As[buf][r * AS + k + tg + 4];
                af[i][3] = As[buf][(r + 8) * AS + k + tg + 4];
            }
            #pragma unroll
            for (int j = 0; j < 8; j++) {
                int c = wn * 64 + j * 8 + g;
                bfr[j][0] = Bs[buf][(k + tg) * BS + c];
                bfr[j][1] = Bs[buf][(k + tg + 4) * BS + c];
            }
            #pragma unroll
            for (int i = 0; i < 2; i++)
                #pragma unroll
                for (int j = 0; j < 8; j++) mma8(acc[i][j], af[i], bfr[j]);
        }
        if (kt < Kt) {
            stores(buf ^ 1);
            __syncthreads();
            buf ^= 1;
        }
    }

    // epilogue
    #pragma unroll
    for (int i = 0; i < 2; i++) {
        int r0 = bm * 128 + wm * 32 + i * 16 + g;
        #pragma unroll
        for (int j = 0; j < 8; j++) {
            int c0 = bn * 128 + wn * 64 + j * 8 + 2 * tg;
            #pragma unroll
            for (int v = 0; v < 4; v++) {
                int r = r0 + (v >> 1) * 8;
                int c = c0 + (v & 1);
                float val = acc[i][j][v] + bias[c];
                if (MODE == 0) {
                    C[(size_t)r * N + c] = val;
                } else {
                    C[(size_t)r * N + c] =
                        xres[(size_t)r * HIDDEN + c] + g_mod[2 * HIDDEN + c] * val;
                }
            }
        }
    }
}

// ---------------- 4) per-head RMSNorm + RoPE (q scaled by D^-1/2) ----------------
__global__ void __launch_bounds__(256) k_qkrope(const float* __restrict__ pe,
                                                const float* __restrict__ qw,
                                                const float* __restrict__ kw) {
    int l = blockIdx.x;
    int warp = threadIdx.x >> 5, lane = threadIdx.x & 31;
    const float sc = 0.08838834764831845f;  // 128^-0.5
    #pragma unroll
    for (int hh = 0; hh < 3; hh++) {
        int h = warp * 3 + hh;
        #pragma unroll
        for (int qk = 0; qk < 2; qk++) {
            const float* src = g_h + (size_t)l * N1 + qk * HIDDEN + h * HDIM;
            const float* w = qk ? kw : qw;
            float4 v = *(const float4*)(src + lane * 4);
            float ss = v.x * v.x + v.y * v.y + v.z * v.z + v.w * v.w;
            for (int o = 16; o; o >>= 1) ss += __shfl_xor_sync(~0u, ss, o);
            float r = rsqrtf(ss * (1.f / HDIM) + 1e-6f);
            float4 w4 = *(const float4*)(w + lane * 4);
            float x0 = v.x * r * w4.x, x1 = v.y * r * w4.y;
            float x2 = v.z * r * w4.z, x3 = v.w * r * w4.w;
            const float* f = pe + (size_t)l * 256 + lane * 8;  // pairs 2*lane, 2*lane+1
            float mul = qk ? 1.f : sc;
            float4 out;
            out.x = (f[0] * x0 + f[1] * x1) * mul;
            out.y = (f[2] * x0 + f[3] * x1) * mul;
            out.z = (f[4] * x2 + f[5] * x3) * mul;
            out.w = (f[6] * x2 + f[7] * x3) * mul;
            float* dst = (qk ? g_k : g_q) + (size_t)l * HIDDEN + h * HDIM + lane * 4;
            *(float4*)dst = out;
        }
    }
}

// ---------------- 5) flash attention (tf32 mma), writes into g_a2[:, :3072] --------
__global__ void __launch_bounds__(64) k_attn() {
    constexpr int KS = 132;  // K tile stride (mod32==4: conflict-free for t/4-row reads)
    constexpr int VS = 136;  // V tile stride (mod32==8: conflict-free for t%4-row reads)
    constexpr int PS = 36;   // P tile stride
    __shared__ uint32_t Ks[32 * KS];
    __shared__ uint32_t Vs[32 * VS];
    __shared__ uint32_t Ps[32 * PS];

    int h = blockIdx.y;
    int q0 = blockIdx.x * 32;
    int tid = threadIdx.x, warp = tid >> 5, lane = tid & 31;
    int g = lane >> 2, tg = lane & 3;

    // Q fragments in registers: warp owns 16 rows (q0+warp*16 .. +15)
    uint32_t qf[16][4];
    const float* qb = g_q + (size_t)(q0 + warp * 16) * HIDDEN + h * HDIM;
    #pragma unroll
    for (int ks = 0; ks < 16; ks++) {
        int d0 = ks * 8 + tg;
        qf[ks][0] = f2tf32(qb[(size_t)g * HIDDEN + d0]);
        qf[ks][1] = f2tf32(qb[(size_t)(g + 8) * HIDDEN + d0]);
        qf[ks][2] = f2tf32(qb[(size_t)g * HIDDEN + d0 + 4]);
        qf[ks][3] = f2tf32(qb[(size_t)(g + 8) * HIDDEN + d0 + 4]);
    }

    float of[16][4];
    #pragma unroll
    for (int j = 0; j < 16; j++)
        #pragma unroll
        for (int v = 0; v < 4; v++) of[j][v] = 0.f;
    float m0 = -1e30f, m1 = -1e30f, l0 = 0.f, l1 = 0.f;

    for (int kv0 = 0; kv0 < LSEQ; kv0 += 32) {
        __syncthreads();
        // cooperative K/V tile load (32 rows x 128)
        #pragma unroll
        for (int i = 0; i < 16; i++) {
            int idx = tid + i * 64;
            int row = idx >> 5;
            int c = (idx & 31) << 2;
            float4 kv = *(const float4*)(g_k + (size_t)(kv0 + row) * HIDDEN + h * HDIM + c);
            *(uint4*)&Ks[row * KS + c] =
                make_uint4(f2tf32(kv.x), f2tf32(kv.y), f2tf32(kv.z), f2tf32(kv.w));
            float4 vv = *(const float4*)(g_h + (size_t)(kv0 + row) * N1 + 2 * HIDDEN + h * HDIM + c);
            *(uint4*)&Vs[row * VS + c] =
                make_uint4(f2tf32(vv.x), f2tf32(vv.y), f2tf32(vv.z), f2tf32(vv.w));
        }
        __syncthreads();

        // S = Q @ K^T  (32 kv cols per warp-tile: 4 n-tiles)
        float s_[4][4];
        #pragma unroll
        for (int j = 0; j < 4; j++)
            #pragma unroll
            for (int v = 0; v < 4; v++) s_[j][v] = 0.f;
        #pragma unroll
        for (int ks = 0; ks < 16; ks++) {
            uint32_t bf[4][2];
            #pragma unroll
            for (int j = 0; j < 4; j++) {
                int n = j * 8 + g;
                bf[j][0] = Ks[n * KS + ks * 8 + tg];
                bf[j][1] = Ks[n * KS + ks * 8 + tg + 4];
            }
            #pragma unroll
            for (int j = 0; j < 4; j++) mma8(s_[j], qf[ks], bf[j]);
        }

        // online softmax (rows g and g+8 of this warp's 16)
        float mx0 = -1e30f, mx1 = -1e30f;
        #pragma unroll
        for (int j = 0; j < 4; j++) {
            mx0 = fmaxf(mx0, fmaxf(s_[j][0], s_[j][1]));
            mx1 = fmaxf(mx1, fmaxf(s_[j][2], s_[j][3]));
        }
        mx0 = fmaxf(mx0, __shfl_xor_sync(~0u, mx0, 1));
        mx0 = fmaxf(mx0, __shfl_xor_sync(~0u, mx0, 2));
        mx1 = fmaxf(mx1, __shfl_xor_sync(~0u, mx1, 1));
        mx1 = fmaxf(mx1, __shfl_xor_sync(~0u, mx1, 2));
        float mn0 = fmaxf(m0, mx0), mn1 = fmaxf(m1, mx1);
        float a0 = __expf(m0 - mn0), a1 = __expf(m1 - mn1);
        float sum0 = 0.f, sum1 = 0.f;
        int pr0 = (warp * 16 + g) * PS;
        int pr1 = (warp * 16 + g + 8) * PS;
        #pragma unroll
        for (int j = 0; j < 4; j++) {
            float p00 = __expf(s_[j][0] - mn0);
            float p01 = __expf(s_[j][1] - mn0);
            float p10 = __expf(s_[j][2] - mn1);
            float p11 = __expf(s_[j][3] - mn1);
            sum0 += p00 + p01;
            sum1 += p10 + p11;
            int c = j * 8 + 2 * tg;
            Ps[pr0 + c] = f2tf32(p00);
            Ps[pr0 + c + 1] = f2tf32(p01);
            Ps[pr1 + c] = f2tf32(p10);
            Ps[pr1 + c + 1] = f2tf32(p11);
        }
        sum0 += __shfl_xor_sync(~0u, sum0, 1);
        sum0 += __shfl_xor_sync(~0u, sum0, 2);
        sum1 += __shfl_xor_sync(~0u, sum1, 1);
        sum1 += __shfl_xor_sync(~0u, sum1, 2);
        l0 = l0 * a0 + sum0;
        l1 = l1 * a1 + sum1;
        m0 = mn0;
        m1 = mn1;
        #pragma unroll
        for (int j = 0; j < 16; j++) {
            of[j][0] *= a0; of[j][1] *= a0;
            of[j][2] *= a1; of[j][3] *= a1;
        }
        __syncwarp();

        // O += P @ V
        #pragma unroll
        for (int ks = 0; ks < 4; ks++) {
            uint32_t af[4];
            int pr = (warp * 16 + g) * PS;
            af[0] = Ps[pr + ks * 8 + tg];
            af[1] = Ps[pr + 8 * PS + ks * 8 + tg];
            af[2] = Ps[pr + ks * 8 + tg + 4];
            af[3] = Ps[pr + 8 * PS + ks * 8 + tg + 4];
            #pragma unroll
            for (int j = 0; j < 16; j++) {
                uint32_t bf2[2];
                bf2[0] = Vs[(ks * 8 + tg) * VS + j * 8 + g];
                bf2[1] = Vs[(ks * 8 + tg + 4) * VS + j * 8 + g];
                mma8(of[j], af, bf2);
            }
        }
    }

    float il0 = 1.f / l0, il1 = 1.f / l1;
    int r0 = q0 + warp * 16 + g;
    int r1 = r0 + 8;
    #pragma unroll
    for (int j = 0; j < 16; j++) {
        int c = h * HDIM + j * 8 + 2 * tg;
        g_a2[(size_t)r0 * NCAT + c]     = of[j][0] * il0;
        g_a2[(size_t)r0 * NCAT + c + 1] = of[j][1] * il0;
        g_a2[(size_t)r1 * NCAT + c]     = of[j][2] * il1;
        g_a2[(size_t)r1 * NCAT + c + 1] = of[j][3] * il1;
    }
}

// ---------------- 6) gelu(mlp) -> g_a2[:, 3072:] ----------------
__global__ void __launch_bounds__(256) k_gelu() {
    int idx = blockIdx.x * 256 + threadIdx.x;  // float4 index, total 2048*3072
    int row = idx / (MLPH / 4);
    int c = (idx % (MLPH / 4)) * 4;
    float4 v = *(const float4*)(g_h + (size_t)row * N1 + 3 * HIDDEN + c);
    float4 o;
    o.x = gelu1(v.x);
    o.y = gelu1(v.y);
    o.z = gelu1(v.z);
    o.w = gelu1(v.w);
    *(float4*)(g_a2 + (size_t)row * NCAT + HIDDEN + c) = o;
}

// ---------------- launch ----------------
extern "C" void kernel_launch(void* const* d_in, const int* in_sizes, int n_in,
                              void* d_out, int out_size) {
    const float* x     = (const float*)d_in[0];
    const float* vec   = (const float*)d_in[1];
    const float* pe    = (const float*)d_in[2];
    const float* w1    = (const float*)d_in[3];
    const float* b1    = (const float*)d_in[4];
    const float* w2    = (const float*)d_in[5];
    const float* b2    = (const float*)d_in[6];
    const float* mod_w = (const float*)d_in[7];
    const float* mod_b = (const float*)d_in[8];
    const float* qw    = (const float*)d_in[9];
    const float* kw    = (const float*)d_in[10];
    float* out = (float*)d_out;

    k_mod<<<NMOD / 256, 256>>>(vec, mod_w, mod_b);
    k_ln<<<LSEQ, 256>>>(x);
    gemm_tf32<0><<<dim3(N1 / 128, LSEQ / 128), 256>>>(w1, b1, nullptr, nullptr);
    k_qkrope<<<LSEQ, 256>>>(pe, qw, kw);
    k_attn<<<dim3(LSEQ / 32, NHEADS), 64>>>();
    k_gelu<<<(LSEQ * (MLPH / 4)) / 256, 256>>>();
    gemm_tf32<1><<<dim3(HIDDEN / 128, LSEQ / 128), 256>>>(w2, b2, out, x);
}

// round 3
// speedup vs baseline: 1.3924x; 1.3924x over previous
#include <cuda_runtime.h>
#include <cuda_fp16.h>
#include <cstdint>

#define HIDDEN 3072
#define NHEADS 24
#define HDIM   128
#define MLPH   12288
#define LSEQ   2048
#define N1     21504   // 3*HIDDEN + MLPH
#define NCAT   15360   // HIDDEN + MLPH
#define NMOD   9216

// ---------------- scratch (static device globals; no allocs) ----------------
__device__ float g_mod[NMOD];
__device__ float g_xmod[LSEQ * HIDDEN];
__device__ float g_h[LSEQ * N1];
__device__ uint32_t g_qh[LSEQ * (HIDDEN / 2)];  // half2-packed q (pairs along d)
__device__ uint32_t g_kh[LSEQ * (HIDDEN / 2)];  // half2-packed k
__device__ float g_a2[LSEQ * NCAT];

// ---------------- helpers ----------------
__device__ __forceinline__ uint32_t pk(float a, float b) {
    __half2 h = __floats2half2_rn(a, b);
    return *(uint32_t*)&h;
}

__device__ __forceinline__ void mma16(float* d, const uint32_t* a, const uint32_t* b) {
    asm volatile(
        "mma.sync.aligned.m16n8k16.row.col.f32.f16.f16.f32 "
        "{%0,%1,%2,%3}, {%4,%5,%6,%7}, {%8,%9}, {%0,%1,%2,%3};"
        : "+f"(d[0]), "+f"(d[1]), "+f"(d[2]), "+f"(d[3])
        : "r"(a[0]), "r"(a[1]), "r"(a[2]), "r"(a[3]), "r"(b[0]), "r"(b[1]));
}

__device__ __forceinline__ float gelu1(float x) {
    float x3 = x * x * x;
    return 0.5f * x * (1.f + tanhf(0.7978845608028654f * (x + 0.044715f * x3)));
}

// ---------------- 1) mod = silu(vec) @ mod_w + mod_b ----------------
__global__ void __launch_bounds__(256) k_mod(const float* __restrict__ vec,
                                             const float* __restrict__ W,
                                             const float* __restrict__ b) {
    __shared__ float sm[HIDDEN];
    for (int i = threadIdx.x; i < HIDDEN; i += 256) {
        float v = vec[i];
        sm[i] = v / (1.f + expf(-v));
    }
    __syncthreads();
    int j = blockIdx.x * 256 + threadIdx.x;
    float s0 = 0.f, s1 = 0.f, s2 = 0.f, s3 = 0.f;
    #pragma unroll 4
    for (int k = 0; k < HIDDEN; k += 4) {
        s0 = fmaf(sm[k + 0], W[(size_t)(k + 0) * NMOD + j], s0);
        s1 = fmaf(sm[k + 1], W[(size_t)(k + 1) * NMOD + j], s1);
        s2 = fmaf(sm[k + 2], W[(size_t)(k + 2) * NMOD + j], s2);
        s3 = fmaf(sm[k + 3], W[(size_t)(k + 3) * NMOD + j], s3);
    }
    g_mod[j] = (s0 + s1) + (s2 + s3) + b[j];
}

// ---------------- 2) x_mod = (1+scale)*LN(x) + shift ----------------
__global__ void __launch_bounds__(256) k_ln(const float* __restrict__ x) {
    int row = blockIdx.x;
    int tid = threadIdx.x;
    const float* xr = x + (size_t)row * HIDDEN;
    float s = 0.f, s2 = 0.f;
    for (int i = tid; i < HIDDEN; i += 256) {
        float v = xr[i];
        s += v;
        s2 = fmaf(v, v, s2);
    }
    __shared__ float rs[8], rs2[8];
    for (int o = 16; o; o >>= 1) {
        s  += __shfl_xor_sync(~0u, s, o);
        s2 += __shfl_xor_sync(~0u, s2, o);
    }
    if ((tid & 31) == 0) { rs[tid >> 5] = s; rs2[tid >> 5] = s2; }
    __syncthreads();
    float ts = 0.f, ts2 = 0.f;
    #pragma unroll
    for (int i = 0; i < 8; i++) { ts += rs[i]; ts2 += rs2[i]; }
    float mu  = ts * (1.f / HIDDEN);
    float var = ts2 * (1.f / HIDDEN) - mu * mu;
    float rstd = rsqrtf(var + 1e-6f);
    float* o = g_xmod + (size_t)row * HIDDEN;
    for (int i = tid; i < HIDDEN; i += 256) {
        float v = (xr[i] - mu) * rstd;
        o[i] = fmaf(g_mod[HIDDEN + i], v, v + g_mod[i]);
    }
}

// ---------------- 3/7) fp16 HMMA GEMM: 128x128 CTA tile, BK=16 ----------------
// MODE 0: g_h = g_xmod @ w1 + b1        (K=3072,  N=21504)
// MODE 1: out = x + gate*(g_a2 @ w2 + b2)  (K=15360, N=3072)
template <int MODE>
__global__ void __launch_bounds__(256) gemm_fp16(const float* __restrict__ Bw,
                                                 const float* __restrict__ bias,
                                                 float* __restrict__ Cout,
                                                 const float* __restrict__ xres) {
    constexpr int K = (MODE == 0) ? HIDDEN : NCAT;
    constexpr int N = (MODE == 0) ? N1 : HIDDEN;
    constexpr int AS = 12;    // uint32 stride per A row (8 used + 4 pad)
    constexpr int BS = 136;   // uint32 stride per B pair-row (128 used + 8 pad)

    __shared__ uint32_t As[2][128 * AS];  // [row][k-pair]
    __shared__ uint32_t Bs[2][8 * BS];    // [k-pair][n]

    const float* A = (MODE == 0) ? g_xmod : g_a2;
    float* C = (MODE == 0) ? g_h : Cout;

    int tid = threadIdx.x;
    int bm = blockIdx.y, bn = blockIdx.x;
    int warp = tid >> 5, lane = tid & 31;
    int wm = warp & 3, wn = warp >> 2;
    int g = lane >> 2, tg = lane & 3;

    int ar = tid >> 2;             // A load row (0..63, +64)
    int ac = (tid & 3) << 2;       // A k-col (0,4,8,12)
    int pr = warp;                 // B pair-row (0..7)
    int bc = lane << 2;            // B n-col

    const float* Aptr = A + (size_t)(bm * 128) * K;
    const float* Bptr = Bw + bn * 128;

    float acc[2][8][4];
    #pragma unroll
    for (int i = 0; i < 2; i++)
        #pragma unroll
        for (int j = 0; j < 8; j++)
            #pragma unroll
            for (int v = 0; v < 4; v++) acc[i][j][v] = 0.f;

    float4 av0, av1, bv0, bv1;
    auto ldg = [&](int k0) {
        av0 = *(const float4*)(Aptr + (size_t)ar * K + k0 + ac);
        av1 = *(const float4*)(Aptr + (size_t)(ar + 64) * K + k0 + ac);
        bv0 = *(const float4*)(Bptr + (size_t)(k0 + 2 * pr) * N + bc);
        bv1 = *(const float4*)(Bptr + (size_t)(k0 + 2 * pr + 1) * N + bc);
    };
    auto sts = [&](int buf) {
        int a2c = (tid & 3) * 2;
        *(uint2*)&As[buf][ar * AS + a2c] = make_uint2(pk(av0.x, av0.y), pk(av0.z, av0.w));
        *(uint2*)&As[buf][(ar + 64) * AS + a2c] = make_uint2(pk(av1.x, av1.y), pk(av1.z, av1.w));
        *(uint4*)&Bs[buf][pr * BS + bc] =
            make_uint4(pk(bv0.x, bv1.x), pk(bv0.y, bv1.y), pk(bv0.z, bv1.z), pk(bv0.w, bv1.w));
    };

    ldg(0);
    sts(0);
    __syncthreads();

    int buf = 0;
    const int Kt = K / 16;
    for (int kt = 1; kt <= Kt; kt++) {
        if (kt < Kt) ldg(kt * 16);
        // compute on buf
        uint32_t af[2][4];
        #pragma unroll
        for (int i = 0; i < 2; i++) {
            int r = wm * 32 + i * 16 + g;
            af[i][0] = As[buf][r * AS + tg];
            af[i][1] = As[buf][(r + 8) * AS + tg];
            af[i][2] = As[buf][r * AS + tg + 4];
            af[i][3] = As[buf][(r + 8) * AS + tg + 4];
        }
        #pragma unroll
        for (int j = 0; j < 8; j++) {
            int c = wn * 64 + j * 8 + g;
            uint32_t bfr[2];
            bfr[0] = Bs[buf][tg * BS + c];
            bfr[1] = Bs[buf][(tg + 4) * BS + c];
            mma16(acc[0][j], af[0], bfr);
            mma16(acc[1][j], af[1], bfr);
        }
        if (kt < Kt) {
            sts(buf ^ 1);
            __syncthreads();
            buf ^= 1;
        }
    }

    // epilogue
    #pragma unroll
    for (int i = 0; i < 2; i++) {
        int r0 = bm * 128 + wm * 32 + i * 16 + g;
        #pragma unroll
        for (int j = 0; j < 8; j++) {
            int c0 = bn * 128 + wn * 64 + j * 8 + 2 * tg;
            #pragma unroll
            for (int v = 0; v < 4; v++) {
                int r = r0 + (v >> 1) * 8;
                int c = c0 + (v & 1);
                float val = acc[i][j][v] + bias[c];
                if (MODE == 0) {
                    C[(size_t)r * N + c] = val;
                } else {
                    C[(size_t)r * N + c] =
                        xres[(size_t)r * HIDDEN + c] + g_mod[2 * HIDDEN + c] * val;
                }
            }
        }
    }
}

// ---------------- 4) per-head RMSNorm + RoPE -> packed half2 q/k ----------------
__global__ void __launch_bounds__(256) k_qkrope(const float* __restrict__ pe,
                                                const float* __restrict__ qw,
                                                const float* __restrict__ kw) {
    int l = blockIdx.x;
    int warp = threadIdx.x >> 5, lane = threadIdx.x & 31;
    const float sc = 0.08838834764831845f;  // 128^-0.5 (folded into q)
    #pragma unroll
    for (int hh = 0; hh < 3; hh++) {
        int h = warp * 3 + hh;
        #pragma unroll
        for (int qk = 0; qk < 2; qk++) {
            const float* src = g_h + (size_t)l * N1 + qk * HIDDEN + h * HDIM;
            const float* w = qk ? kw : qw;
            float4 v = *(const float4*)(src + lane * 4);
            float ss = v.x * v.x + v.y * v.y + v.z * v.z + v.w * v.w;
            for (int o = 16; o; o >>= 1) ss += __shfl_xor_sync(~0u, ss, o);
            float r = rsqrtf(ss * (1.f / HDIM) + 1e-6f);
            float4 w4 = *(const float4*)(w + lane * 4);
            float x0 = v.x * r * w4.x, x1 = v.y * r * w4.y;
            float x2 = v.z * r * w4.z, x3 = v.w * r * w4.w;
            const float* f = pe + (size_t)l * 256 + lane * 8;
            float mul = qk ? 1.f : sc;
            float o0 = (f[0] * x0 + f[1] * x1) * mul;
            float o1 = (f[2] * x0 + f[3] * x1) * mul;
            float o2 = (f[4] * x2 + f[5] * x3) * mul;
            float o3 = (f[6] * x2 + f[7] * x3) * mul;
            uint32_t* dst = (qk ? g_kh : g_qh) + (size_t)l * (HIDDEN / 2) + h * 64 + lane * 2;
            dst[0] = pk(o0, o1);
            dst[1] = pk(o2, o3);
        }
    }
}

// ---------------- 5) flash attention (fp16 HMMA) ----------------
__global__ void __launch_bounds__(64) k_attn() {
    constexpr int KS = 68;   // Ks2 row stride (64 d-pairs + 4)
    constexpr int VS = 136;  // Vs2 pair-row stride (128 d + 8)
    constexpr int PS = 20;   // Ps2 row stride (16 kv-pairs + 4)
    __shared__ uint32_t Ks[32 * KS];   // [kv][d-pair]
    __shared__ uint32_t Vs[16 * VS];   // [kv-pair][d]
    __shared__ uint32_t Ps[32 * PS];   // [row][kv-pair]

    int h = blockIdx.y;
    int q0 = blockIdx.x * 32;
    int tid = threadIdx.x, warp = tid >> 5, lane = tid & 31;
    int g = lane >> 2, tg = lane & 3;

    // Q fragments: warp owns rows q0+warp*16 .. +15; 8 k-steps of k16
    uint32_t qf[8][4];
    const uint32_t* qb = g_qh + (size_t)(q0 + warp * 16) * (HIDDEN / 2) + h * 64;
    #pragma unroll
    for (int ks = 0; ks < 8; ks++) {
        qf[ks][0] = qb[(size_t)g * (HIDDEN / 2) + ks * 8 + tg];
        qf[ks][1] = qb[(size_t)(g + 8) * (HIDDEN / 2) + ks * 8 + tg];
        qf[ks][2] = qb[(size_t)g * (HIDDEN / 2) + ks * 8 + tg + 4];
        qf[ks][3] = qb[(size_t)(g + 8) * (HIDDEN / 2) + ks * 8 + tg + 4];
    }

    float of[16][4];
    #pragma unroll
    for (int j = 0; j < 16; j++)
        #pragma unroll
        for (int v = 0; v < 4; v++) of[j][v] = 0.f;
    float m0 = -1e30f, m1 = -1e30f, l0 = 0.f, l1 = 0.f;

    for (int kv0 = 0; kv0 < LSEQ; kv0 += 32) {
        __syncthreads();
        // K staging: 32 rows x 64 d-pairs
        #pragma unroll
        for (int i = 0; i < 16; i++) {
            int idx = tid + i * 64;
            int row = idx >> 5;
            int c4 = idx & 31;  // float4 index along d
            const uint32_t* kr = g_kh + (size_t)(kv0 + row) * (HIDDEN / 2) + h * 64;
            *(uint2*)&Ks[row * KS + c4 * 2] = *(const uint2*)(kr + c4 * 2);
        }
        // V staging: 16 pair-rows x 128 d (pack across kv rows)
        #pragma unroll
        for (int i = 0; i < 8; i++) {
            int idx = tid + i * 64;
            int vpr = idx >> 5;        // kv pair-row (0..15)
            int c4 = idx & 31;
            const float* v0 = g_h + (size_t)(kv0 + 2 * vpr) * N1 + 2 * HIDDEN + h * HDIM + c4 * 4;
            const float* v1 = v0 + N1;
            float4 a = *(const float4*)v0;
            float4 b = *(const float4*)v1;
            *(uint4*)&Vs[vpr * VS + c4 * 4] =
                make_uint4(pk(a.x, b.x), pk(a.y, b.y), pk(a.z, b.z), pk(a.w, b.w));
        }
        __syncthreads();

        // S = Q @ K^T
        float s_[4][4];
        #pragma unroll
        for (int j = 0; j < 4; j++)
            #pragma unroll
            for (int v = 0; v < 4; v++) s_[j][v] = 0.f;
        #pragma unroll
        for (int ks = 0; ks < 8; ks++) {
            #pragma unroll
            for (int j = 0; j < 4; j++) {
                int n = j * 8 + g;
                uint32_t bf[2];
                bf[0] = Ks[n * KS + ks * 8 + tg];
                bf[1] = Ks[n * KS + ks * 8 + tg + 4];
                mma16(s_[j], qf[ks], bf);
            }
        }

        // online softmax
        float mx0 = -1e30f, mx1 = -1e30f;
        #pragma unroll
        for (int j = 0; j < 4; j++) {
            mx0 = fmaxf(mx0, fmaxf(s_[j][0], s_[j][1]));
            mx1 = fmaxf(mx1, fmaxf(s_[j][2], s_[j][3]));
        }
        mx0 = fmaxf(mx0, __shfl_xor_sync(~0u, mx0, 1));
        mx0 = fmaxf(mx0, __shfl_xor_sync(~0u, mx0, 2));
        mx1 = fmaxf(mx1, __shfl_xor_sync(~0u, mx1, 1));
        mx1 = fmaxf(mx1, __shfl_xor_sync(~0u, mx1, 2));
        float mn0 = fmaxf(m0, mx0), mn1 = fmaxf(m1, mx1);
        float a0 = __expf(m0 - mn0), a1 = __expf(m1 - mn1);
        float sum0 = 0.f, sum1 = 0.f;
        int pr0 = (warp * 16 + g) * PS;
        int pr1 = (warp * 16 + g + 8) * PS;
        #pragma unroll
        for (int j = 0; j < 4; j++) {
            float p00 = __expf(s_[j][0] - mn0);
            float p01 = __expf(s_[j][1] - mn0);
            float p10 = __expf(s_[j][2] - mn1);
            float p11 = __expf(s_[j][3] - mn1);
            sum0 += p00 + p01;
            sum1 += p10 + p11;
            Ps[pr0 + j * 4 + tg] = pk(p00, p01);
            Ps[pr1 + j * 4 + tg] = pk(p10, p11);
        }
        sum0 += __shfl_xor_sync(~0u, sum0, 1);
        sum0 += __shfl_xor_sync(~0u, sum0, 2);
        sum1 += __shfl_xor_sync(~0u, sum1, 1);
        sum1 += __shfl_xor_sync(~0u, sum1, 2);
        l0 = l0 * a0 + sum0;
        l1 = l1 * a1 + sum1;
        m0 = mn0;
        m1 = mn1;
        #pragma unroll
        for (int j = 0; j < 16; j++) {
            of[j][0] *= a0; of[j][1] *= a0;
            of[j][2] *= a1; of[j][3] *= a1;
        }
        __syncwarp();

        // O += P @ V  (2 k-steps of k16 over 32 kv)
        #pragma unroll
        for (int ks = 0; ks < 2; ks++) {
            uint32_t af[4];
            af[0] = Ps[(warp * 16 + g) * PS + ks * 8 + tg];
            af[1] = Ps[(warp * 16 + g + 8) * PS + ks * 8 + tg];
            af[2] = Ps[(warp * 16 + g) * PS + ks * 8 + tg + 4];
            af[3] = Ps[(warp * 16 + g + 8) * PS + ks * 8 + tg + 4];
            #pragma unroll
            for (int j = 0; j < 16; j++) {
                uint32_t bf2[2];
                bf2[0] = Vs[(ks * 8 + tg) * VS + j * 8 + g];
                bf2[1] = Vs[(ks * 8 + tg + 4) * VS + j * 8 + g];
                mma16(of[j], af, bf2);
            }
        }
    }

    float il0 = 1.f / l0, il1 = 1.f / l1;
    int r0 = q0 + warp * 16 + g;
    int r1 = r0 + 8;
    #pragma unroll
    for (int j = 0; j < 16; j++) {
        int c = h * HDIM + j * 8 + 2 * tg;
        g_a2[(size_t)r0 * NCAT + c]     = of[j][0] * il0;
        g_a2[(size_t)r0 * NCAT + c + 1] = of[j][1] * il0;
        g_a2[(size_t)r1 * NCAT + c]     = of[j][2] * il1;
        g_a2[(size_t)r1 * NCAT + c + 1] = of[j][3] * il1;
    }
}

// ---------------- 6) gelu(mlp) -> g_a2[:, 3072:] ----------------
__global__ void __launch_bounds__(256) k_gelu() {
    int idx = blockIdx.x * 256 + threadIdx.x;
    int row = idx / (MLPH / 4);
    int c = (idx % (MLPH / 4)) * 4;
    float4 v = *(const float4*)(g_h + (size_t)row * N1 + 3 * HIDDEN + c);
    float4 o;
    o.x = gelu1(v.x);
    o.y = gelu1(v.y);
    o.z = gelu1(v.z);
    o.w = gelu1(v.w);
    *(float4*)(g_a2 + (size_t)row * NCAT + HIDDEN + c) = o;
}

// ---------------- launch ----------------
extern "C" void kernel_launch(void* const* d_in, const int* in_sizes, int n_in,
                              void* d_out, int out_size) {
    const float* x     = (const float*)d_in[0];
    const float* vec   = (const float*)d_in[1];
    const float* pe    = (const float*)d_in[2];
    const float* w1    = (const float*)d_in[3];
    const float* b1    = (const float*)d_in[4];
    const float* w2    = (const float*)d_in[5];
    const float* b2    = (const float*)d_in[6];
    const float* mod_w = (const float*)d_in[7];
    const float* mod_b = (const float*)d_in[8];
    const float* qw    = (const float*)d_in[9];
    const float* kw    = (const float*)d_in[10];
    float* out = (float*)d_out;

    k_mod<<<NMOD / 256, 256>>>(vec, mod_w, mod_b);
    k_ln<<<LSEQ, 256>>>(x);
    gemm_fp16<0><<<dim3(N1 / 128, LSEQ / 128), 256>>>(w1, b1, nullptr, nullptr);
    k_qkrope<<<LSEQ, 256>>>(pe, qw, kw);
    k_attn<<<dim3(LSEQ / 32, NHEADS), 64>>>();
    k_gelu<<<(LSEQ * (MLPH / 4)) / 256, 256>>>();
    gemm_fp16<1><<<dim3(HIDDEN / 128, LSEQ / 128), 256>>>(w2, b2, out, x);
}

// round 4
// speedup vs baseline: 2.0630x; 1.4816x over previous
#include <cuda_runtime.h>
#include <cuda_fp16.h>
#include <cstdint>

#define HIDDEN 3072
#define NHEADS 24
#define HDIM   128
#define MLPH   12288
#define LSEQ   2048
#define N1     21504   // 3*HIDDEN + MLPH
#define NCAT   15360   // HIDDEN + MLPH
#define NMOD   9216

// ---------------- scratch (static device globals; no allocs) ----------------
__device__ float g_mod[NMOD];
__device__ __half g_xmodh[LSEQ * HIDDEN];
__device__ float g_h[LSEQ * N1];
__device__ uint32_t g_qh[LSEQ * (HIDDEN / 2)];
__device__ uint32_t g_kh[LSEQ * (HIDDEN / 2)];
__device__ __half g_a2h[LSEQ * NCAT];
__device__ __half g_w1h[(size_t)HIDDEN * N1];
__device__ __half g_w2h[(size_t)NCAT * HIDDEN];

// ---------------- helpers ----------------
__device__ __forceinline__ uint32_t pk(float a, float b) {
    __half2 h = __floats2half2_rn(a, b);
    return *(uint32_t*)&h;
}

__device__ __forceinline__ void mma16(float* d, const uint32_t* a, const uint32_t* b) {
    asm volatile(
        "mma.sync.aligned.m16n8k16.row.col.f32.f16.f16.f32 "
        "{%0,%1,%2,%3}, {%4,%5,%6,%7}, {%8,%9}, {%0,%1,%2,%3};"
        : "+f"(d[0]), "+f"(d[1]), "+f"(d[2]), "+f"(d[3])
        : "r"(a[0]), "r"(a[1]), "r"(a[2]), "r"(a[3]), "r"(b[0]), "r"(b[1]));
}

__device__ __forceinline__ float gelu1(float x) {
    float x3 = x * x * x;
    return 0.5f * x * (1.f + tanhf(0.7978845608028654f * (x + 0.044715f * x3)));
}

__device__ __forceinline__ uint32_t smem_u32(const void* p) {
    uint32_t a;
    asm("{ .reg .u64 t; cvta.to.shared.u64 t, %1; cvt.u32.u64 %0, t; }" : "=r"(a) : "l"(p));
    return a;
}

#define CP16(dst, src) \
    asm volatile("cp.async.cg.shared.global [%0], [%1], 16;" :: "r"(dst), "l"(src))

// ---------------- 0) f32 -> f16 weight conversion ----------------
__global__ void __launch_bounds__(256) k_cvt(const float* __restrict__ src,
                                             __half* __restrict__ dst) {
    size_t i = ((size_t)blockIdx.x * 256 + threadIdx.x) * 4;
    float4 v = *(const float4*)(src + i);
    *(uint32_t*)(dst + i) = pk(v.x, v.y);
    *(uint32_t*)(dst + i + 2) = pk(v.z, v.w);
}

// ---------------- 1) mod = silu(vec) @ mod_w + mod_b ----------------
__global__ void __launch_bounds__(256) k_mod(const float* __restrict__ vec,
                                             const float* __restrict__ W,
                                             const float* __restrict__ b) {
    __shared__ float sm[HIDDEN];
    for (int i = threadIdx.x; i < HIDDEN; i += 256) {
        float v = vec[i];
        sm[i] = v / (1.f + expf(-v));
    }
    __syncthreads();
    int j = blockIdx.x * 256 + threadIdx.x;
    float s0 = 0.f, s1 = 0.f, s2 = 0.f, s3 = 0.f;
    #pragma unroll 4
    for (int k = 0; k < HIDDEN; k += 4) {
        s0 = fmaf(sm[k + 0], W[(size_t)(k + 0) * NMOD + j], s0);
        s1 = fmaf(sm[k + 1], W[(size_t)(k + 1) * NMOD + j], s1);
        s2 = fmaf(sm[k + 2], W[(size_t)(k + 2) * NMOD + j], s2);
        s3 = fmaf(sm[k + 3], W[(size_t)(k + 3) * NMOD + j], s3);
    }
    g_mod[j] = (s0 + s1) + (s2 + s3) + b[j];
}

// ---------------- 2) x_mod = (1+scale)*LN(x) + shift -> fp16 ----------------
__global__ void __launch_bounds__(256) k_ln(const float* __restrict__ x) {
    int row = blockIdx.x;
    int tid = threadIdx.x;
    const float* xr = x + (size_t)row * HIDDEN;
    float s = 0.f, s2 = 0.f;
    for (int i = tid; i < HIDDEN; i += 256) {
        float v = xr[i];
        s += v;
        s2 = fmaf(v, v, s2);
    }
    __shared__ float rs[8], rs2[8];
    for (int o = 16; o; o >>= 1) {
        s  += __shfl_xor_sync(~0u, s, o);
        s2 += __shfl_xor_sync(~0u, s2, o);
    }
    if ((tid & 31) == 0) { rs[tid >> 5] = s; rs2[tid >> 5] = s2; }
    __syncthreads();
    float ts = 0.f, ts2 = 0.f;
    #pragma unroll
    for (int i = 0; i < 8; i++) { ts += rs[i]; ts2 += rs2[i]; }
    float mu  = ts * (1.f / HIDDEN);
    float var = ts2 * (1.f / HIDDEN) - mu * mu;
    float rstd = rsqrtf(var + 1e-6f);
    for (int i = tid * 2; i < HIDDEN; i += 512) {
        float v0 = (xr[i] - mu) * rstd;
        float v1 = (xr[i + 1] - mu) * rstd;
        v0 = fmaf(g_mod[HIDDEN + i], v0, v0 + g_mod[i]);
        v1 = fmaf(g_mod[HIDDEN + i + 1], v1, v1 + g_mod[i + 1]);
        *(uint32_t*)&g_xmodh[(size_t)row * HIDDEN + i] = pk(v0, v1);
    }
}

// ---------------- 3/7) fp16 HMMA GEMM, cp.async 3-stage + ldmatrix ----------------
// MODE 0: g_h = xmod @ w1 + b1           (K=3072,  N=21504)
// MODE 1: out = x + gate*(a2 @ w2 + b2)  (K=15360, N=3072)
// smem per stage: A 128x(32h, 80B stride) = 10240B ; B 32x(128h, swizzled) = 8192B
template <int MODE>
__global__ void __launch_bounds__(256, 2) gemm_cp(const __half* __restrict__ Bh,
                                                  const float* __restrict__ bias,
                                                  float* __restrict__ Cout,
                                                  const float* __restrict__ xres) {
    constexpr int K = (MODE == 0) ? HIDDEN : NCAT;
    constexpr int N = (MODE == 0) ? N1 : HIDDEN;
    constexpr int Kt = K / 32;
    constexpr int STG = 18432;  // bytes per stage

    extern __shared__ char smem[];
    const __half* Ah = (MODE == 0) ? g_xmodh : g_a2h;
    float* C = (MODE == 0) ? g_h : Cout;

    int tid = threadIdx.x;
    int bm = blockIdx.x, bn = blockIdx.y;
    int warp = tid >> 5, lane = tid & 31;
    int wm = warp & 3, wn = warp >> 2;
    int g = lane >> 2, tg = lane & 3;
    uint32_t sb = smem_u32(smem);

    auto issue = [&](int kt, int stage) {
        uint32_t sA = sb + stage * STG;
        uint32_t sB = sA + 10240;
        int kb = kt * 32;
        #pragma unroll
        for (int i = 0; i < 2; i++) {
            int op = tid + 256 * i;
            int arow = op >> 2, achk = op & 3;
            uint32_t dst = sA + arow * 80 + achk * 16;
            const __half* src = Ah + (size_t)(bm * 128 + arow) * K + kb + achk * 8;
            CP16(dst, src);
        }
        #pragma unroll
        for (int i = 0; i < 2; i++) {
            int op = tid + 256 * i;
            int krow = op >> 4, bchk = op & 15;
            uint32_t dst = sB + krow * 256 + ((bchk ^ (krow & 7)) << 4);
            const __half* src = Bh + (size_t)(kb + krow) * N + bn * 128 + bchk * 8;
            CP16(dst, src);
        }
        asm volatile("cp.async.commit_group;" ::: "memory");
    };

    float acc[2][8][4];
    #pragma unroll
    for (int i = 0; i < 2; i++)
        #pragma unroll
        for (int j = 0; j < 8; j++)
            #pragma unroll
            for (int v = 0; v < 4; v++) acc[i][j][v] = 0.f;

    issue(0, 0);
    issue(1, 1);

    for (int kt = 0; kt < Kt; kt++) {
        int st = kt % 3;
        if (kt + 2 < Kt) issue(kt + 2, (kt + 2) % 3);
        else asm volatile("cp.async.commit_group;" ::: "memory");
        asm volatile("cp.async.wait_group 2;" ::: "memory");
        __syncthreads();

        uint32_t sA = sb + st * STG;
        uint32_t sB = sA + 10240;
        #pragma unroll
        for (int s = 0; s < 2; s++) {
            uint32_t af[2][4];
            #pragma unroll
            for (int i = 0; i < 2; i++) {
                int row = wm * 32 + i * 16 + (lane & 7) + ((lane >> 3) & 1) * 8;
                int chunk = 2 * s + (lane >> 4);
                uint32_t ad = sA + row * 80 + chunk * 16;
                asm volatile("ldmatrix.sync.aligned.m8n8.x4.shared.b16 {%0,%1,%2,%3}, [%4];"
                             : "=r"(af[i][0]), "=r"(af[i][1]), "=r"(af[i][2]), "=r"(af[i][3])
                             : "r"(ad));
            }
            #pragma unroll
            for (int t = 0; t < 4; t++) {
                int j = 2 * t;
                int i2 = lane >> 3;
                int krow = s * 16 + (i2 & 1) * 8 + (lane & 7);
                int chunk = wn * 8 + j + (i2 >> 1);
                uint32_t ad = sB + krow * 256 + ((chunk ^ (krow & 7)) << 4);
                uint32_t b0, b1, b2, b3;
                asm volatile("ldmatrix.sync.aligned.m8n8.x4.trans.shared.b16 {%0,%1,%2,%3}, [%4];"
                             : "=r"(b0), "=r"(b1), "=r"(b2), "=r"(b3) : "r"(ad));
                uint32_t bA[2] = {b0, b1}, bB[2] = {b2, b3};
                mma16(acc[0][j], af[0], bA);
                mma16(acc[1][j], af[1], bA);
                mma16(acc[0][j + 1], af[0], bB);
                mma16(acc[1][j + 1], af[1], bB);
            }
        }
        __syncthreads();
    }

    // epilogue
    #pragma unroll
    for (int i = 0; i < 2; i++) {
        int r0 = bm * 128 + wm * 32 + i * 16 + g;
        #pragma unroll
        for (int j = 0; j < 8; j++) {
            int c0 = bn * 128 + wn * 64 + j * 8 + 2 * tg;
            #pragma unroll
            for (int v = 0; v < 4; v++) {
                int r = r0 + (v >> 1) * 8;
                int c = c0 + (v & 1);
                float val = acc[i][j][v] + bias[c];
                if (MODE == 0) {
                    C[(size_t)r * N + c] = val;
                } else {
                    C[(size_t)r * N + c] =
                        xres[(size_t)r * HIDDEN + c] + g_mod[2 * HIDDEN + c] * val;
                }
            }
        }
    }
}

// ---------------- 4) per-head RMSNorm + RoPE -> packed half2 q/k ----------------
__global__ void __launch_bounds__(256) k_qkrope(const float* __restrict__ pe,
                                                const float* __restrict__ qw,
                                                const float* __restrict__ kw) {
    int l = blockIdx.x;
    int warp = threadIdx.x >> 5, lane = threadIdx.x & 31;
    const float sc = 0.08838834764831845f;  // 128^-0.5 folded into q
    #pragma unroll
    for (int hh = 0; hh < 3; hh++) {
        int h = warp * 3 + hh;
        #pragma unroll
        for (int qk = 0; qk < 2; qk++) {
            const float* src = g_h + (size_t)l * N1 + qk * HIDDEN + h * HDIM;
            const float* w = qk ? kw : qw;
            float4 v = *(const float4*)(src + lane * 4);
            float ss = v.x * v.x + v.y * v.y + v.z * v.z + v.w * v.w;
            for (int o = 16; o; o >>= 1) ss += __shfl_xor_sync(~0u, ss, o);
            float r = rsqrtf(ss * (1.f / HDIM) + 1e-6f);
            float4 w4 = *(const float4*)(w + lane * 4);
            float x0 = v.x * r * w4.x, x1 = v.y * r * w4.y;
            float x2 = v.z * r * w4.z, x3 = v.w * r * w4.w;
            const float* f = pe + (size_t)l * 256 + lane * 8;
            float mul = qk ? 1.f : sc;
            float o0 = (f[0] * x0 + f[1] * x1) * mul;
            float o1 = (f[2] * x0 + f[3] * x1) * mul;
            float o2 = (f[4] * x2 + f[5] * x3) * mul;
            float o3 = (f[6] * x2 + f[7] * x3) * mul;
            uint32_t* dst = (qk ? g_kh : g_qh) + (size_t)l * (HIDDEN / 2) + h * 64 + lane * 2;
            dst[0] = pk(o0, o1);
            dst[1] = pk(o2, o3);
        }
    }
}

// ---------------- 5) flash attention (fp16 HMMA, fixed-shift softmax) ----------------
__global__ void __launch_bounds__(64) k_attn() {
    constexpr int KS = 68;
    constexpr int VS = 136;
    constexpr int PS = 20;
    constexpr float SHIFT = 10.0f;
    __shared__ uint32_t Ks[32 * KS];
    __shared__ uint32_t Vs[16 * VS];
    __shared__ uint32_t Ps[32 * PS];

    int h = blockIdx.y;
    int q0 = blockIdx.x * 32;
    int tid = threadIdx.x, warp = tid >> 5, lane = tid & 31;
    int g = lane >> 2, tg = lane & 3;

    uint32_t qf[8][4];
    const uint32_t* qb = g_qh + (size_t)(q0 + warp * 16) * (HIDDEN / 2) + h * 64;
    #pragma unroll
    for (int ks = 0; ks < 8; ks++) {
        qf[ks][0] = qb[(size_t)g * (HIDDEN / 2) + ks * 8 + tg];
        qf[ks][1] = qb[(size_t)(g + 8) * (HIDDEN / 2) + ks * 8 + tg];
        qf[ks][2] = qb[(size_t)g * (HIDDEN / 2) + ks * 8 + tg + 4];
        qf[ks][3] = qb[(size_t)(g + 8) * (HIDDEN / 2) + ks * 8 + tg + 4];
    }

    float of[16][4];
    #pragma unroll
    for (int j = 0; j < 16; j++)
        #pragma unroll
        for (int v = 0; v < 4; v++) of[j][v] = 0.f;
    float l0 = 0.f, l1 = 0.f;

    for (int kv0 = 0; kv0 < LSEQ; kv0 += 32) {
        __syncthreads();
        #pragma unroll
        for (int i = 0; i < 16; i++) {
            int idx = tid + i * 64;
            int row = idx >> 5;
            int c4 = idx & 31;
            const uint32_t* kr = g_kh + (size_t)(kv0 + row) * (HIDDEN / 2) + h * 64;
            *(uint2*)&Ks[row * KS + c4 * 2] = *(const uint2*)(kr + c4 * 2);
        }
        #pragma unroll
        for (int i = 0; i < 8; i++) {
            int idx = tid + i * 64;
            int vpr = idx >> 5;
            int c4 = idx & 31;
            const float* v0 = g_h + (size_t)(kv0 + 2 * vpr) * N1 + 2 * HIDDEN + h * HDIM + c4 * 4;
            const float* v1 = v0 + N1;
            float4 a = *(const float4*)v0;
            float4 b = *(const float4*)v1;
            *(uint4*)&Vs[vpr * VS + c4 * 4] =
                make_uint4(pk(a.x, b.x), pk(a.y, b.y), pk(a.z, b.z), pk(a.w, b.w));
        }
        __syncthreads();

        float s_[4][4];
        #pragma unroll
        for (int j = 0; j < 4; j++)
            #pragma unroll
            for (int v = 0; v < 4; v++) s_[j][v] = 0.f;
        #pragma unroll
        for (int ks = 0; ks < 8; ks++) {
            #pragma unroll
            for (int j = 0; j < 4; j++) {
                int n = j * 8 + g;
                uint32_t bf[2];
                bf[0] = Ks[n * KS + ks * 8 + tg];
                bf[1] = Ks[n * KS + ks * 8 + tg + 4];
                mma16(s_[j], qf[ks], bf);
            }
        }

        float sum0 = 0.f, sum1 = 0.f;
        int pr0 = (warp * 16 + g) * PS;
        int pr1 = (warp * 16 + g + 8) * PS;
        #pragma unroll
        for (int j = 0; j < 4; j++) {
            float p00 = __expf(s_[j][0] - SHIFT);
            float p01 = __expf(s_[j][1] - SHIFT);
            float p10 = __expf(s_[j][2] - SHIFT);
            float p11 = __expf(s_[j][3] - SHIFT);
            sum0 += p00 + p01;
            sum1 += p10 + p11;
            Ps[pr0 + j * 4 + tg] = pk(p00, p01);
            Ps[pr1 + j * 4 + tg] = pk(p10, p11);
        }
        sum0 += __shfl_xor_sync(~0u, sum0, 1);
        sum0 += __shfl_xor_sync(~0u, sum0, 2);
        sum1 += __shfl_xor_sync(~0u, sum1, 1);
        sum1 += __shfl_xor_sync(~0u, sum1, 2);
        l0 += sum0;
        l1 += sum1;
        __syncwarp();

        #pragma unroll
        for (int ks = 0; ks < 2; ks++) {
            uint32_t af[4];
            af[0] = Ps[(warp * 16 + g) * PS + ks * 8 + tg];
            af[1] = Ps[(warp * 16 + g + 8) * PS + ks * 8 + tg];
            af[2] = Ps[(warp * 16 + g) * PS + ks * 8 + tg + 4];
            af[3] = Ps[(warp * 16 + g + 8) * PS + ks * 8 + tg + 4];
            #pragma unroll
            for (int j = 0; j < 16; j++) {
                uint32_t bf2[2];
                bf2[0] = Vs[(ks * 8 + tg) * VS + j * 8 + g];
                bf2[1] = Vs[(ks * 8 + tg + 4) * VS + j * 8 + g];
                mma16(of[j], af, bf2);
            }
        }
        __syncwarp();
    }

    float il0 = 1.f / l0, il1 = 1.f / l1;
    int r0 = q0 + warp * 16 + g;
    int r1 = r0 + 8;
    #pragma unroll
    for (int j = 0; j < 16; j++) {
        int c = h * HDIM + j * 8 + 2 * tg;
        *(uint32_t*)&g_a2h[(size_t)r0 * NCAT + c] = pk(of[j][0] * il0, of[j][1] * il0);
        *(uint32_t*)&g_a2h[(size_t)r1 * NCAT + c] = pk(of[j][2] * il1, of[j][3] * il1);
    }
}

// ---------------- 6) gelu(mlp) -> g_a2h[:, 3072:] ----------------
__global__ void __launch_bounds__(256) k_gelu() {
    int idx = blockIdx.x * 256 + threadIdx.x;
    int row = idx / (MLPH / 4);
    int c = (idx % (MLPH / 4)) * 4;
    float4 v = *(const float4*)(g_h + (size_t)row * N1 + 3 * HIDDEN + c);
    __half* dst = g_a2h + (size_t)row * NCAT + HIDDEN + c;
    *(uint32_t*)dst = pk(gelu1(v.x), gelu1(v.y));
    *(uint32_t*)(dst + 2) = pk(gelu1(v.z), gelu1(v.w));
}

// ---------------- launch ----------------
extern "C" void kernel_launch(void* const* d_in, const int* in_sizes, int n_in,
                              void* d_out, int out_size) {
    const float* x     = (const float*)d_in[0];
    const float* vec   = (const float*)d_in[1];
    const float* pe    = (const float*)d_in[2];
    const float* w1    = (const float*)d_in[3];
    const float* b1    = (const float*)d_in[4];
    const float* w2    = (const float*)d_in[5];
    const float* b2    = (const float*)d_in[6];
    const float* mod_w = (const float*)d_in[7];
    const float* mod_b = (const float*)d_in[8];
    const float* qw    = (const float*)d_in[9];
    const float* kw    = (const float*)d_in[10];
    float* out = (float*)d_out;

    __half* w1h;  cudaGetSymbolAddress((void**)&w1h, g_w1h);
    __half* w2h;  cudaGetSymbolAddress((void**)&w2h, g_w2h);

    cudaFuncSetAttribute(gemm_cp<0>, cudaFuncAttributeMaxDynamicSharedMemorySize, 3 * 18432);
    cudaFuncSetAttribute(gemm_cp<1>, cudaFuncAttributeMaxDynamicSharedMemorySize, 3 * 18432);

    k_cvt<<<(HIDDEN * (N1 / 4)) / 256, 256>>>(w1, w1h);
    k_cvt<<<(NCAT * (HIDDEN / 4)) / 256, 256>>>(w2, w2h);
    k_mod<<<NMOD / 256, 256>>>(vec, mod_w, mod_b);
    k_ln<<<LSEQ, 256>>>(x);
    gemm_cp<0><<<dim3(LSEQ / 128, N1 / 128), 256, 3 * 18432>>>(w1h, b1, nullptr, nullptr);
    k_qkrope<<<LSEQ, 256>>>(pe, qw, kw);
    k_attn<<<dim3(LSEQ / 32, NHEADS), 64>>>();
    k_gelu<<<(LSEQ * (MLPH / 4)) / 256, 256>>>();
    gemm_cp<1><<<dim3(LSEQ / 128, HIDDEN / 128), 256, 3 * 18432>>>(w2h, b2, out, x);
}

// round 5
// speedup vs baseline: 2.6178x; 1.2689x over previous
#include <cuda_runtime.h>
#include <cuda_fp16.h>
#include <cstdint>

#define HIDDEN 3072
#define NHEADS 24
#define HDIM   128
#define MLPH   12288
#define LSEQ   2048
#define N1     21504   // 3*HIDDEN + MLPH
#define NCAT   15360   // HIDDEN + MLPH
#define NMOD   9216

// ---------------- scratch (static device globals; no allocs) ----------------
__device__ float g_mod[NMOD];
__device__ __half g_xmodh[LSEQ * HIDDEN];
__device__ __half g_h[(size_t)LSEQ * NMOD];     // qkv (fp16)
__device__ uint32_t g_qh[LSEQ * (HIDDEN / 2)];
__device__ uint32_t g_kh[LSEQ * (HIDDEN / 2)];
__device__ __half g_a2h[(size_t)LSEQ * NCAT];
__device__ __half g_w1h[(size_t)HIDDEN * N1];
__device__ __half g_w2h[(size_t)NCAT * HIDDEN];

// ---------------- helpers ----------------
__device__ __forceinline__ uint32_t pk(float a, float b) {
    __half2 h = __floats2half2_rn(a, b);
    return *(uint32_t*)&h;
}

__device__ __forceinline__ void mma16(float* d, const uint32_t* a, const uint32_t* b) {
    asm volatile(
        "mma.sync.aligned.m16n8k16.row.col.f32.f16.f16.f32 "
        "{%0,%1,%2,%3}, {%4,%5,%6,%7}, {%8,%9}, {%0,%1,%2,%3};"
        : "+f"(d[0]), "+f"(d[1]), "+f"(d[2]), "+f"(d[3])
        : "r"(a[0]), "r"(a[1]), "r"(a[2]), "r"(a[3]), "r"(b[0]), "r"(b[1]));
}

__device__ __forceinline__ float gelu1(float x) {
    float x3 = x * x * x;
    return 0.5f * x * (1.f + tanhf(0.7978845608028654f * (x + 0.044715f * x3)));
}

__device__ __forceinline__ uint32_t smem_u32(const void* p) {
    uint32_t a;
    asm("{ .reg .u64 t; cvta.to.shared.u64 t, %1; cvt.u32.u64 %0, t; }" : "=r"(a) : "l"(p));
    return a;
}

#define CP16(dst, src) \
    asm volatile("cp.async.cg.shared.global [%0], [%1], 16;" :: "r"(dst), "l"(src))
#define CP_COMMIT() asm volatile("cp.async.commit_group;" ::: "memory")
#define CP_WAIT1()  asm volatile("cp.async.wait_group 1;" ::: "memory")

#define LDM_X4(r0, r1, r2, r3, ad) \
    asm volatile("ldmatrix.sync.aligned.m8n8.x4.shared.b16 {%0,%1,%2,%3}, [%4];" \
                 : "=r"(r0), "=r"(r1), "=r"(r2), "=r"(r3) : "r"(ad))
#define LDM_X4T(r0, r1, r2, r3, ad) \
    asm volatile("ldmatrix.sync.aligned.m8n8.x4.trans.shared.b16 {%0,%1,%2,%3}, [%4];" \
                 : "=r"(r0), "=r"(r1), "=r"(r2), "=r"(r3) : "r"(ad))

// ---------------- 0) f32 -> f16 weight conversion ----------------
__global__ void __launch_bounds__(256) k_cvt(const float* __restrict__ src,
                                             __half* __restrict__ dst) {
    size_t i = ((size_t)blockIdx.x * 256 + threadIdx.x) * 4;
    float4 v = *(const float4*)(src + i);
    *(uint32_t*)(dst + i) = pk(v.x, v.y);
    *(uint32_t*)(dst + i + 2) = pk(v.z, v.w);
}

// ---------------- 1) mod = silu(vec) @ mod_w + mod_b ----------------
__global__ void __launch_bounds__(256) k_mod(const float* __restrict__ vec,
                                             const float* __restrict__ W,
                                             const float* __restrict__ b) {
    __shared__ float sm[HIDDEN];
    for (int i = threadIdx.x; i < HIDDEN; i += 256) {
        float v = vec[i];
        sm[i] = v / (1.f + expf(-v));
    }
    __syncthreads();
    int j = blockIdx.x * 256 + threadIdx.x;
    float s0 = 0.f, s1 = 0.f, s2 = 0.f, s3 = 0.f;
    #pragma unroll 4
    for (int k = 0; k < HIDDEN; k += 4) {
        s0 = fmaf(sm[k + 0], W[(size_t)(k + 0) * NMOD + j], s0);
        s1 = fmaf(sm[k + 1], W[(size_t)(k + 1) * NMOD + j], s1);
        s2 = fmaf(sm[k + 2], W[(size_t)(k + 2) * NMOD + j], s2);
        s3 = fmaf(sm[k + 3], W[(size_t)(k + 3) * NMOD + j], s3);
    }
    g_mod[j] = (s0 + s1) + (s2 + s3) + b[j];
}

// ---------------- 2) x_mod = (1+scale)*LN(x) + shift -> fp16 ----------------
__global__ void __launch_bounds__(256) k_ln(const float* __restrict__ x) {
    int row = blockIdx.x;
    int tid = threadIdx.x;
    const float* xr = x + (size_t)row * HIDDEN;
    float s = 0.f, s2 = 0.f;
    for (int i = tid; i < HIDDEN; i += 256) {
        float v = xr[i];
        s += v;
        s2 = fmaf(v, v, s2);
    }
    __shared__ float rs[8], rs2[8];
    for (int o = 16; o; o >>= 1) {
        s  += __shfl_xor_sync(~0u, s, o);
        s2 += __shfl_xor_sync(~0u, s2, o);
    }
    if ((tid & 31) == 0) { rs[tid >> 5] = s; rs2[tid >> 5] = s2; }
    __syncthreads();
    float ts = 0.f, ts2 = 0.f;
    #pragma unroll
    for (int i = 0; i < 8; i++) { ts += rs[i]; ts2 += rs2[i]; }
    float mu  = ts * (1.f / HIDDEN);
    float var = ts2 * (1.f / HIDDEN) - mu * mu;
    float rstd = rsqrtf(var + 1e-6f);
    for (int i = tid * 2; i < HIDDEN; i += 512) {
        float v0 = (xr[i] - mu) * rstd;
        float v1 = (xr[i + 1] - mu) * rstd;
        v0 = fmaf(g_mod[HIDDEN + i], v0, v0 + g_mod[i]);
        v1 = fmaf(g_mod[HIDDEN + i + 1], v1, v1 + g_mod[i + 1]);
        *(uint32_t*)&g_xmodh[(size_t)row * HIDDEN + i] = pk(v0, v1);
    }
}

// ---------------- 3/7) fp16 HMMA GEMM, cp.async 3-stage, 1 sync/iter ----------------
// MODE 0: h = xmod @ w1 + b1; qkv tiles -> g_h (fp16), mlp tiles -> gelu -> g_a2h
// MODE 1: out = x + gate*(a2 @ w2 + b2)  (fp32 out)
template <int MODE>
__global__ void __launch_bounds__(256, 2) gemm_cp(const __half* __restrict__ Bh,
                                                  const float* __restrict__ bias,
                                                  float* __restrict__ Cout,
                                                  const float* __restrict__ xres) {
    constexpr int K = (MODE == 0) ? HIDDEN : NCAT;
    constexpr int N = (MODE == 0) ? N1 : HIDDEN;
    constexpr int Kt = K / 32;
    constexpr int STG = 18432;

    extern __shared__ char smem[];
    const __half* Ah = (MODE == 0) ? g_xmodh : g_a2h;

    int tid = threadIdx.x;
    int bm = blockIdx.x, bn = blockIdx.y;
    int warp = tid >> 5, lane = tid & 31;
    int wm = warp & 3, wn = warp >> 2;
    int g = lane >> 2, tg = lane & 3;
    uint32_t sb = smem_u32(smem);

    auto issue = [&](int kt, int stage) {
        uint32_t sA = sb + stage * STG;
        uint32_t sB = sA + 10240;
        int kb = kt * 32;
        #pragma unroll
        for (int i = 0; i < 2; i++) {
            int op = tid + 256 * i;
            int arow = op >> 2, achk = op & 3;
            uint32_t dst = sA + arow * 80 + achk * 16;
            const __half* src = Ah + (size_t)(bm * 128 + arow) * K + kb + achk * 8;
            CP16(dst, src);
        }
        #pragma unroll
        for (int i = 0; i < 2; i++) {
            int op = tid + 256 * i;
            int krow = op >> 4, bchk = op & 15;
            uint32_t dst = sB + krow * 256 + ((bchk ^ (krow & 7)) << 4);
            const __half* src = Bh + (size_t)(kb + krow) * N + bn * 128 + bchk * 8;
            CP16(dst, src);
        }
        CP_COMMIT();
    };

    float acc[2][8][4];
    #pragma unroll
    for (int i = 0; i < 2; i++)
        #pragma unroll
        for (int j = 0; j < 8; j++)
            #pragma unroll
            for (int v = 0; v < 4; v++) acc[i][j][v] = 0.f;

    issue(0, 0);
    issue(1, 1);

    for (int kt = 0; kt < Kt; kt++) {
        int st = kt % 3;
        CP_WAIT1();
        __syncthreads();
        if (kt + 2 < Kt) issue(kt + 2, (kt + 2) % 3);
        else CP_COMMIT();

        uint32_t sA = sb + st * STG;
        uint32_t sB = sA + 10240;
        #pragma unroll
        for (int s = 0; s < 2; s++) {
            uint32_t af[2][4];
            #pragma unroll
            for (int i = 0; i < 2; i++) {
                int row = wm * 32 + i * 16 + (lane & 7) + ((lane >> 3) & 1) * 8;
                int chunk = 2 * s + (lane >> 4);
                uint32_t ad = sA + row * 80 + chunk * 16;
                LDM_X4(af[i][0], af[i][1], af[i][2], af[i][3], ad);
            }
            #pragma unroll
            for (int t = 0; t < 4; t++) {
                int j = 2 * t;
                int i2 = lane >> 3;
                int krow = s * 16 + (i2 & 1) * 8 + (lane & 7);
                int chunk = wn * 8 + j + (i2 >> 1);
                uint32_t ad = sB + krow * 256 + ((chunk ^ (krow & 7)) << 4);
                uint32_t b0, b1, b2, b3;
                LDM_X4T(b0, b1, b2, b3, ad);
                uint32_t bA[2] = {b0, b1}, bB[2] = {b2, b3};
                mma16(acc[0][j], af[0], bA);
                mma16(acc[1][j], af[1], bA);
                mma16(acc[0][j + 1], af[0], bB);
                mma16(acc[1][j + 1], af[1], bB);
            }
        }
    }
    __syncthreads();

    // epilogue
    #pragma unroll
    for (int i = 0; i < 2; i++) {
        int r = bm * 128 + wm * 32 + i * 16 + g;
        #pragma unroll
        for (int j = 0; j < 8; j++) {
            int c = bn * 128 + wn * 64 + j * 8 + 2 * tg;
            float bb0 = bias[c], bb1 = bias[c + 1];
            float v00 = acc[i][j][0] + bb0, v01 = acc[i][j][1] + bb1;  // row r
            float v10 = acc[i][j][2] + bb0, v11 = acc[i][j][3] + bb1;  // row r+8
            if (MODE == 0) {
                if (bn < 72) {
                    *(uint32_t*)&g_h[(size_t)r * NMOD + c] = pk(v00, v01);
                    *(uint32_t*)&g_h[(size_t)(r + 8) * NMOD + c] = pk(v10, v11);
                } else {
                    int cc = c - NMOD + HIDDEN;
                    *(uint32_t*)&g_a2h[(size_t)r * NCAT + cc] = pk(gelu1(v00), gelu1(v01));
                    *(uint32_t*)&g_a2h[(size_t)(r + 8) * NCAT + cc] = pk(gelu1(v10), gelu1(v11));
                }
            } else {
                Cout[(size_t)r * HIDDEN + c] =
                    xres[(size_t)r * HIDDEN + c] + g_mod[2 * HIDDEN + c] * v00;
                Cout[(size_t)r * HIDDEN + c + 1] =
                    xres[(size_t)r * HIDDEN + c + 1] + g_mod[2 * HIDDEN + c + 1] * v01;
                Cout[(size_t)(r + 8) * HIDDEN + c] =
                    xres[(size_t)(r + 8) * HIDDEN + c] + g_mod[2 * HIDDEN + c] * v10;
                Cout[(size_t)(r + 8) * HIDDEN + c + 1] =
                    xres[(size_t)(r + 8) * HIDDEN + c + 1] + g_mod[2 * HIDDEN + c + 1] * v11;
            }
        }
    }
}

// ---------------- 4) per-head RMSNorm + RoPE -> packed half2 q/k ----------------
__global__ void __launch_bounds__(256) k_qkrope(const float* __restrict__ pe,
                                                const float* __restrict__ qw,
                                                const float* __restrict__ kw) {
    int l = blockIdx.x;
    int warp = threadIdx.x >> 5, lane = threadIdx.x & 31;
    const float sc = 0.08838834764831845f;  // 128^-0.5 folded into q
    #pragma unroll
    for (int hh = 0; hh < 3; hh++) {
        int h = warp * 3 + hh;
        #pragma unroll
        for (int qk = 0; qk < 2; qk++) {
            const __half* src = g_h + (size_t)l * NMOD + qk * HIDDEN + h * HDIM + lane * 4;
            const float* w = qk ? kw : qw;
            __half2 h0 = *(const __half2*)src;
            __half2 h1 = *(const __half2*)(src + 2);
            float2 va = __half22float2(h0);
            float2 vb = __half22float2(h1);
            float ss = va.x * va.x + va.y * va.y + vb.x * vb.x + vb.y * vb.y;
            for (int o = 16; o; o >>= 1) ss += __shfl_xor_sync(~0u, ss, o);
            float r = rsqrtf(ss * (1.f / HDIM) + 1e-6f);
            float4 w4 = *(const float4*)(w + lane * 4);
            float x0 = va.x * r * w4.x, x1 = va.y * r * w4.y;
            float x2 = vb.x * r * w4.z, x3 = vb.y * r * w4.w;
            const float* f = pe + (size_t)l * 256 + lane * 8;
            float mul = qk ? 1.f : sc;
            float o0 = (f[0] * x0 + f[1] * x1) * mul;
            float o1 = (f[2] * x0 + f[3] * x1) * mul;
            float o2 = (f[4] * x2 + f[5] * x3) * mul;
            float o3 = (f[6] * x2 + f[7] * x3) * mul;
            uint32_t* dst = (qk ? g_kh : g_qh) + (size_t)l * (HIDDEN / 2) + h * 64 + lane * 2;
            dst[0] = pk(o0, o1);
            dst[1] = pk(o2, o3);
        }
    }
}

// ---------------- 5) flash attention: Br=64, Bc=32, 4 warps, 3-stage cp.async ----------------
__global__ void __launch_bounds__(128) k_attn() {
    constexpr float SHIFT = 10.0f;
    __shared__ __align__(16) char sm[3 * 16384];  // per stage: K 8KB + V 8KB

    int h = blockIdx.y;
    int q0 = blockIdx.x * 64;
    int tid = threadIdx.x, warp = tid >> 5, lane = tid & 31;
    int g = lane >> 2, tg = lane & 3;
    uint32_t sbase = smem_u32(sm);

    auto stage = [&](int t, int s) {
        int kv0 = t * 32;
        uint32_t base = sbase + s * 16384;
        #pragma unroll
        for (int i = 0; i < 4; i++) {  // K tile: 32 rows x 256B
            int op = i * 128 + tid;
            int r = op >> 4, c = op & 15;
            uint32_t dst = base + r * 256 + ((c ^ (r & 7)) << 4);
            const char* src = (const char*)g_kh + (size_t)(kv0 + r) * (HIDDEN * 2) + h * 256 + c * 16;
            CP16(dst, src);
        }
        #pragma unroll
        for (int i = 0; i < 4; i++) {  // V tile: 32 rows x 256B
            int op = i * 128 + tid;
            int r = op >> 4, c = op & 15;
            uint32_t dst = base + 8192 + r * 256 + ((c ^ (r & 7)) << 4);
            const char* src = (const char*)g_h + ((size_t)(kv0 + r) * NMOD + 2 * HIDDEN + h * HDIM) * 2 + c * 16;
            CP16(dst, src);
        }
        CP_COMMIT();
    };

    // Q fragments: warp rows q0+warp*16 + {g, g+8}; 8 k16-steps over d
    uint32_t qf[8][4];
    const uint32_t* qb = g_qh + (size_t)(q0 + warp * 16) * (HIDDEN / 2) + h * 64;
    #pragma unroll
    for (int ks = 0; ks < 8; ks++) {
        qf[ks][0] = qb[(size_t)g * (HIDDEN / 2) + ks * 8 + tg];
        qf[ks][1] = qb[(size_t)(g + 8) * (HIDDEN / 2) + ks * 8 + tg];
        qf[ks][2] = qb[(size_t)g * (HIDDEN / 2) + ks * 8 + tg + 4];
        qf[ks][3] = qb[(size_t)(g + 8) * (HIDDEN / 2) + ks * 8 + tg + 4];
    }

    float of[16][4];
    #pragma unroll
    for (int j = 0; j < 16; j++)
        #pragma unroll
        for (int v = 0; v < 4; v++) of[j][v] = 0.f;
    float l0 = 0.f, l1 = 0.f;

    stage(0, 0);
    stage(1, 1);

    for (int t = 0; t < LSEQ / 32; t++) {
        int st = t % 3;
        CP_WAIT1();
        __syncthreads();
        if (t + 2 < LSEQ / 32) stage(t + 2, (t + 2) % 3);
        else CP_COMMIT();

        uint32_t kbase = sbase + st * 16384;
        uint32_t vbase = kbase + 8192;

        // S = Q @ K^T  (n = 32 kv)
        float s_[4][4];
        #pragma unroll
        for (int j = 0; j < 4; j++)
            #pragma unroll
            for (int v = 0; v < 4; v++) s_[j][v] = 0.f;
        #pragma unroll
        for (int ks = 0; ks < 8; ks++) {
            #pragma unroll
            for (int hn = 0; hn < 2; hn++) {
                int r = hn * 16 + ((lane >> 4) << 3) + (lane & 7);
                int c = 2 * ks + ((lane >> 3) & 1);
                uint32_t ad = kbase + r * 256 + ((c ^ (r & 7)) << 4);
                uint32_t b0, b1, b2, b3;
                LDM_X4(b0, b1, b2, b3, ad);
                uint32_t bA[2] = {b0, b1}, bB[2] = {b2, b3};
                mma16(s_[2 * hn], qf[ks], bA);
                mma16(s_[2 * hn + 1], qf[ks], bB);
            }
        }

        // softmax (fixed shift) — P stays in registers
        #pragma unroll
        for (int j = 0; j < 4; j++) {
            s_[j][0] = __expf(s_[j][0] - SHIFT);
            s_[j][1] = __expf(s_[j][1] - SHIFT);
            s_[j][2] = __expf(s_[j][2] - SHIFT);
            s_[j][3] = __expf(s_[j][3] - SHIFT);
            l0 += s_[j][0] + s_[j][1];
            l1 += s_[j][2] + s_[j][3];
        }

        // O += P @ V
        #pragma unroll
        for (int ks2 = 0; ks2 < 2; ks2++) {
            uint32_t af[4];
            af[0] = pk(s_[2 * ks2][0], s_[2 * ks2][1]);
            af[1] = pk(s_[2 * ks2][2], s_[2 * ks2][3]);
            af[2] = pk(s_[2 * ks2 + 1][0], s_[2 * ks2 + 1][1]);
            af[3] = pk(s_[2 * ks2 + 1][2], s_[2 * ks2 + 1][3]);
            #pragma unroll
            for (int tt = 0; tt < 8; tt++) {
                int r = ks2 * 16 + ((lane >> 3) & 1) * 8 + (lane & 7);
                int c = 2 * tt + (lane >> 4);
                uint32_t ad = vbase + r * 256 + ((c ^ (r & 7)) << 4);
                uint32_t b0, b1, b2, b3;
                LDM_X4T(b0, b1, b2, b3, ad);
                uint32_t bA[2] = {b0, b1}, bB[2] = {b2, b3};
                mma16(of[2 * tt], af, bA);
                mma16(of[2 * tt + 1], af, bB);
            }
        }
    }

    l0 += __shfl_xor_sync(~0u, l0, 1);
    l0 += __shfl_xor_sync(~0u, l0, 2);
    l1 += __shfl_xor_sync(~0u, l1, 1);
    l1 += __shfl_xor_sync(~0u, l1, 2);
    float il0 = 1.f / l0, il1 = 1.f / l1;
    int r0 = q0 + warp * 16 + g;
    int r1 = r0 + 8;
    #pragma unroll
    for (int j = 0; j < 16; j++) {
        int c = h * HDIM + j * 8 + 2 * tg;
        *(uint32_t*)&g_a2h[(size_t)r0 * NCAT + c] = pk(of[j][0] * il0, of[j][1] * il0);
        *(uint32_t*)&g_a2h[(size_t)r1 * NCAT + c] = pk(of[j][2] * il1, of[j][3] * il1);
    }
}

// ---------------- launch ----------------
extern "C" void kernel_launch(void* const* d_in, const int* in_sizes, int n_in,
                              void* d_out, int out_size) {
    const float* x     = (const float*)d_in[0];
    const float* vec   = (const float*)d_in[1];
    const float* pe    = (const float*)d_in[2];
    const float* w1    = (const float*)d_in[3];
    const float* b1    = (const float*)d_in[4];
    const float* w2    = (const float*)d_in[5];
    const float* b2    = (const float*)d_in[6];
    const float* mod_w = (const float*)d_in[7];
    const float* mod_b = (const float*)d_in[8];
    const float* qw    = (const float*)d_in[9];
    const float* kw    = (const float*)d_in[10];
    float* out = (float*)d_out;

    __half* w1h;  cudaGetSymbolAddress((void**)&w1h, g_w1h);
    __half* w2h;  cudaGetSymbolAddress((void**)&w2h, g_w2h);

    cudaFuncSetAttribute(gemm_cp<0>, cudaFuncAttributeMaxDynamicSharedMemorySize, 3 * 18432);
    cudaFuncSetAttribute(gemm_cp<1>, cudaFuncAttributeMaxDynamicSharedMemorySize, 3 * 18432);

    k_cvt<<<(HIDDEN * (N1 / 4)) / 256, 256>>>(w1, w1h);
    k_cvt<<<(NCAT * (HIDDEN / 4)) / 256, 256>>>(w2, w2h);
    k_mod<<<NMOD / 256, 256>>>(vec, mod_w, mod_b);
    k_ln<<<LSEQ, 256>>>(x);
    gemm_cp<0><<<dim3(LSEQ / 128, N1 / 128), 256, 3 * 18432>>>(w1h, b1, nullptr, nullptr);
    k_qkrope<<<LSEQ, 256>>>(pe, qw, kw);
    k_attn<<<dim3(LSEQ / 64, NHEADS), 128>>>();
    gemm_cp<1><<<dim3(LSEQ / 128, HIDDEN / 128), 256, 3 * 18432>>>(w2h, b2, out, x);
}

// round 6
// speedup vs baseline: 2.8484x; 1.0881x over previous
#include <cuda_runtime.h>
#include <cuda_fp16.h>
#include <cstdint>

#define HIDDEN 3072
#define NHEADS 24
#define HDIM   128
#define MLPH   12288
#define LSEQ   2048
#define N1     21504   // 3*HIDDEN + MLPH
#define NCAT   15360   // HIDDEN + MLPH
#define NMOD   9216

// ---------------- scratch (static device globals; no allocs) ----------------
__device__ float g_mod[NMOD];
__device__ __half g_xmodh[LSEQ * HIDDEN];
__device__ __half g_h[(size_t)LSEQ * NMOD];     // qkv (fp16)
__device__ uint32_t g_qh[LSEQ * (HIDDEN / 2)];
__device__ uint32_t g_kh[LSEQ * (HIDDEN / 2)];
__device__ __half g_a2h[(size_t)LSEQ * NCAT];
__device__ __half g_w1h[(size_t)HIDDEN * N1];
__device__ __half g_w2h[(size_t)NCAT * HIDDEN];

// ---------------- helpers ----------------
__device__ __forceinline__ uint32_t pk(float a, float b) {
    __half2 h = __floats2half2_rn(a, b);
    return *(uint32_t*)&h;
}

__device__ __forceinline__ void mma16(float* d, const uint32_t* a, const uint32_t* b) {
    asm volatile(
        "mma.sync.aligned.m16n8k16.row.col.f32.f16.f16.f32 "
        "{%0,%1,%2,%3}, {%4,%5,%6,%7}, {%8,%9}, {%0,%1,%2,%3};"
        : "+f"(d[0]), "+f"(d[1]), "+f"(d[2]), "+f"(d[3])
        : "r"(a[0]), "r"(a[1]), "r"(a[2]), "r"(a[3]), "r"(b[0]), "r"(b[1]));
}

__device__ __forceinline__ float gelu1(float x) {
    float x3 = x * x * x;
    return 0.5f * x * (1.f + tanhf(0.7978845608028654f * (x + 0.044715f * x3)));
}

__device__ __forceinline__ uint32_t smem_u32(const void* p) {
    uint32_t a;
    asm("{ .reg .u64 t; cvta.to.shared.u64 t, %1; cvt.u32.u64 %0, t; }" : "=r"(a) : "l"(p));
    return a;
}

#define CP16(dst, src) \
    asm volatile("cp.async.cg.shared.global [%0], [%1], 16;" :: "r"(dst), "l"(src))
#define CP_COMMIT() asm volatile("cp.async.commit_group;" ::: "memory")
#define CP_WAIT2()  asm volatile("cp.async.wait_group 2;" ::: "memory")
#define CP_WAIT1()  asm volatile("cp.async.wait_group 1;" ::: "memory")

#define LDM_X4(r0, r1, r2, r3, ad) \
    asm volatile("ldmatrix.sync.aligned.m8n8.x4.shared.b16 {%0,%1,%2,%3}, [%4];" \
                 : "=r"(r0), "=r"(r1), "=r"(r2), "=r"(r3) : "r"(ad))
#define LDM_X4T(r0, r1, r2, r3, ad) \
    asm volatile("ldmatrix.sync.aligned.m8n8.x4.trans.shared.b16 {%0,%1,%2,%3}, [%4];" \
                 : "=r"(r0), "=r"(r1), "=r"(r2), "=r"(r3) : "r"(ad))

// ---------------- 0) f32 -> f16 weight conversion ----------------
__global__ void __launch_bounds__(256) k_cvt(const float* __restrict__ src,
                                             __half* __restrict__ dst) {
    size_t i = ((size_t)blockIdx.x * 256 + threadIdx.x) * 4;
    float4 v = *(const float4*)(src + i);
    *(uint32_t*)(dst + i) = pk(v.x, v.y);
    *(uint32_t*)(dst + i + 2) = pk(v.z, v.w);
}

// ---------------- 1) mod = silu(vec) @ mod_w + mod_b ----------------
__global__ void __launch_bounds__(256) k_mod(const float* __restrict__ vec,
                                             const float* __restrict__ W,
                                             const float* __restrict__ b) {
    __shared__ float sm[HIDDEN];
    for (int i = threadIdx.x; i < HIDDEN; i += 256) {
        float v = vec[i];
        sm[i] = v / (1.f + expf(-v));
    }
    __syncthreads();
    int j = blockIdx.x * 256 + threadIdx.x;
    float s0 = 0.f, s1 = 0.f, s2 = 0.f, s3 = 0.f;
    #pragma unroll 4
    for (int k = 0; k < HIDDEN; k += 4) {
        s0 = fmaf(sm[k + 0], W[(size_t)(k + 0) * NMOD + j], s0);
        s1 = fmaf(sm[k + 1], W[(size_t)(k + 1) * NMOD + j], s1);
        s2 = fmaf(sm[k + 2], W[(size_t)(k + 2) * NMOD + j], s2);
        s3 = fmaf(sm[k + 3], W[(size_t)(k + 3) * NMOD + j], s3);
    }
    g_mod[j] = (s0 + s1) + (s2 + s3) + b[j];
}

// ---------------- 2) x_mod = (1+scale)*LN(x) + shift -> fp16 (one pass) --------
__global__ void __launch_bounds__(256) k_ln(const float* __restrict__ x) {
    int row = blockIdx.x;
    int tid = threadIdx.x;
    const float* xr = x + (size_t)row * HIDDEN;
    float2 xv[6];
    float s = 0.f, s2 = 0.f;
    #pragma unroll
    for (int i = 0; i < 6; i++) {
        xv[i] = *(const float2*)(xr + tid * 2 + i * 512);
        s += xv[i].x + xv[i].y;
        s2 = fmaf(xv[i].x, xv[i].x, fmaf(xv[i].y, xv[i].y, s2));
    }
    __shared__ float rs[8], rs2[8];
    for (int o = 16; o; o >>= 1) {
        s  += __shfl_xor_sync(~0u, s, o);
        s2 += __shfl_xor_sync(~0u, s2, o);
    }
    if ((tid & 31) == 0) { rs[tid >> 5] = s; rs2[tid >> 5] = s2; }
    __syncthreads();
    float ts = 0.f, ts2 = 0.f;
    #pragma unroll
    for (int i = 0; i < 8; i++) { ts += rs[i]; ts2 += rs2[i]; }
    float mu  = ts * (1.f / HIDDEN);
    float var = ts2 * (1.f / HIDDEN) - mu * mu;
    float rstd = rsqrtf(var + 1e-6f);
    #pragma unroll
    for (int i = 0; i < 6; i++) {
        int c = tid * 2 + i * 512;
        float v0 = (xv[i].x - mu) * rstd;
        float v1 = (xv[i].y - mu) * rstd;
        v0 = fmaf(g_mod[HIDDEN + c], v0, v0 + g_mod[c]);
        v1 = fmaf(g_mod[HIDDEN + c + 1], v1, v1 + g_mod[c + 1]);
        *(uint32_t*)&g_xmodh[(size_t)row * HIDDEN + c] = pk(v0, v1);
    }
}

// ---------------- 3/7) fp16 HMMA GEMM, cp.async 4-stage, 1 sync/iter ----------------
// MODE 0: h = xmod @ w1 + b1; qkv -> g_h (fp16), mlp -> gelu -> g_a2h   [128x128, 256 thr]
// MODE 1: out = x + gate*(a2 @ w2 + b2)                                  [64x128, 128 thr]
template <int MODE>
__global__ void __launch_bounds__(MODE == 0 ? 256 : 128, MODE == 0 ? 2 : 3)
gemm_cp(const __half* __restrict__ Bh, const float* __restrict__ bias,
        float* __restrict__ Cout, const float* __restrict__ xres) {
    constexpr int K = (MODE == 0) ? HIDDEN : NCAT;
    constexpr int N = (MODE == 0) ? N1 : HIDDEN;
    constexpr int MT = (MODE == 0) ? 128 : 64;
    constexpr int THREADS = MT * 2;
    constexpr int Kt = K / 32;
    constexpr int STG = MT * 80 + 8192;
    constexpr int WMM = MT / 32;  // warps along m

    extern __shared__ char smem[];
    const __half* Ah = (MODE == 0) ? g_xmodh : g_a2h;

    int tid = threadIdx.x;
    int bm = blockIdx.x, bn = blockIdx.y;
    int warp = tid >> 5, lane = tid & 31;
    int wm = warp % WMM, wn = warp / WMM;
    int g = lane >> 2, tg = lane & 3;
    uint32_t sb = smem_u32(smem);

    auto issue = [&](int kt, int stage) {
        uint32_t sA = sb + stage * STG;
        uint32_t sB = sA + MT * 80;
        int kb = kt * 32;
        #pragma unroll
        for (int i = 0; i < 2; i++) {
            int op = tid + THREADS * i;
            int arow = op >> 2, achk = op & 3;
            uint32_t dst = sA + arow * 80 + achk * 16;
            const __half* src = Ah + (size_t)(bm * MT + arow) * K + kb + achk * 8;
            CP16(dst, src);
        }
        #pragma unroll
        for (int i = 0; i < 512 / THREADS; i++) {
            int op = tid + THREADS * i;
            int krow = op >> 4, bchk = op & 15;
            uint32_t dst = sB + krow * 256 + ((bchk ^ (krow & 7)) << 4);
            const __half* src = Bh + (size_t)(kb + krow) * N + bn * 128 + bchk * 8;
            CP16(dst, src);
        }
        CP_COMMIT();
    };

    float acc[2][8][4];
    #pragma unroll
    for (int i = 0; i < 2; i++)
        #pragma unroll
        for (int j = 0; j < 8; j++)
            #pragma unroll
            for (int v = 0; v < 4; v++) acc[i][j][v] = 0.f;

    issue(0, 0);
    issue(1, 1);
    issue(2, 2);

    for (int kt = 0; kt < Kt; kt++) {
        int st = kt & 3;
        CP_WAIT2();
        __syncthreads();
        if (kt + 3 < Kt) issue(kt + 3, (kt + 3) & 3);
        else CP_COMMIT();

        uint32_t sA = sb + st * STG;
        uint32_t sB = sA + MT * 80;
        #pragma unroll
        for (int s = 0; s < 2; s++) {
            uint32_t af[2][4];
            #pragma unroll
            for (int i = 0; i < 2; i++) {
                int row = wm * 32 + i * 16 + (lane & 7) + ((lane >> 3) & 1) * 8;
                int chunk = 2 * s + (lane >> 4);
                uint32_t ad = sA + row * 80 + chunk * 16;
                LDM_X4(af[i][0], af[i][1], af[i][2], af[i][3], ad);
            }
            #pragma unroll
            for (int t = 0; t < 4; t++) {
                int j = 2 * t;
                int i2 = lane >> 3;
                int krow = s * 16 + (i2 & 1) * 8 + (lane & 7);
                int chunk = wn * 8 + j + (i2 >> 1);
                uint32_t ad = sB + krow * 256 + ((chunk ^ (krow & 7)) << 4);
                uint32_t b0, b1, b2, b3;
                LDM_X4T(b0, b1, b2, b3, ad);
                uint32_t bA[2] = {b0, b1}, bB[2] = {b2, b3};
                mma16(acc[0][j], af[0], bA);
                mma16(acc[1][j], af[1], bA);
                mma16(acc[0][j + 1], af[0], bB);
                mma16(acc[1][j + 1], af[1], bB);
            }
        }
    }
    __syncthreads();

    // epilogue
    #pragma unroll
    for (int i = 0; i < 2; i++) {
        int r = bm * MT + wm * 32 + i * 16 + g;
        #pragma unroll
        for (int j = 0; j < 8; j++) {
            int c = bn * 128 + wn * 64 + j * 8 + 2 * tg;
            float bb0 = bias[c], bb1 = bias[c + 1];
            float v00 = acc[i][j][0] + bb0, v01 = acc[i][j][1] + bb1;  // row r
            float v10 = acc[i][j][2] + bb0, v11 = acc[i][j][3] + bb1;  // row r+8
            if (MODE == 0) {
                if (bn < 72) {
                    *(uint32_t*)&g_h[(size_t)r * NMOD + c] = pk(v00, v01);
                    *(uint32_t*)&g_h[(size_t)(r + 8) * NMOD + c] = pk(v10, v11);
                } else {
                    int cc = c - NMOD + HIDDEN;
                    *(uint32_t*)&g_a2h[(size_t)r * NCAT + cc] = pk(gelu1(v00), gelu1(v01));
                    *(uint32_t*)&g_a2h[(size_t)(r + 8) * NCAT + cc] = pk(gelu1(v10), gelu1(v11));
                }
            } else {
                Cout[(size_t)r * HIDDEN + c] =
                    xres[(size_t)r * HIDDEN + c] + g_mod[2 * HIDDEN + c] * v00;
                Cout[(size_t)r * HIDDEN + c + 1] =
                    xres[(size_t)r * HIDDEN + c + 1] + g_mod[2 * HIDDEN + c + 1] * v01;
                Cout[(size_t)(r + 8) * HIDDEN + c] =
                    xres[(size_t)(r + 8) * HIDDEN + c] + g_mod[2 * HIDDEN + c] * v10;
                Cout[(size_t)(r + 8) * HIDDEN + c + 1] =
                    xres[(size_t)(r + 8) * HIDDEN + c + 1] + g_mod[2 * HIDDEN + c + 1] * v11;
            }
        }
    }
}

// ---------------- 4) per-head RMSNorm + RoPE -> packed half2 q/k ----------------
__global__ void __launch_bounds__(256) k_qkrope(const float* __restrict__ pe,
                                                const float* __restrict__ qw,
                                                const float* __restrict__ kw) {
    int l = blockIdx.x;
    int warp = threadIdx.x >> 5, lane = threadIdx.x & 31;
    const float sc = 0.08838834764831845f;  // 128^-0.5 folded into q
    #pragma unroll
    for (int hh = 0; hh < 3; hh++) {
        int h = warp * 3 + hh;
        #pragma unroll
        for (int qk = 0; qk < 2; qk++) {
            const __half* src = g_h + (size_t)l * NMOD + qk * HIDDEN + h * HDIM + lane * 4;
            const float* w = qk ? kw : qw;
            __half2 h0 = *(const __half2*)src;
            __half2 h1 = *(const __half2*)(src + 2);
            float2 va = __half22float2(h0);
            float2 vb = __half22float2(h1);
            float ss = va.x * va.x + va.y * va.y + vb.x * vb.x + vb.y * vb.y;
            for (int o = 16; o; o >>= 1) ss += __shfl_xor_sync(~0u, ss, o);
            float r = rsqrtf(ss * (1.f / HDIM) + 1e-6f);
            float4 w4 = *(const float4*)(w + lane * 4);
            float x0 = va.x * r * w4.x, x1 = va.y * r * w4.y;
            float x2 = vb.x * r * w4.z, x3 = vb.y * r * w4.w;
            const float* f = pe + (size_t)l * 256 + lane * 8;
            float mul = qk ? 1.f : sc;
            float o0 = (f[0] * x0 + f[1] * x1) * mul;
            float o1 = (f[2] * x0 + f[3] * x1) * mul;
            float o2 = (f[4] * x2 + f[5] * x3) * mul;
            float o3 = (f[6] * x2 + f[7] * x3) * mul;
            uint32_t* dst = (qk ? g_kh : g_qh) + (size_t)l * (HIDDEN / 2) + h * 64 + lane * 2;
            dst[0] = pk(o0, o1);
            dst[1] = pk(o2, o3);
        }
    }
}

// ---------------- 5) flash attention: Br=64, Bc=32, 4 warps, 3-stage cp.async ----------------
__global__ void __launch_bounds__(128) k_attn() {
    constexpr float SHIFT = 10.0f;
    __shared__ __align__(16) char sm[3 * 16384];  // per stage: K 8KB + V 8KB

    int h = blockIdx.y;
    int q0 = blockIdx.x * 64;
    int tid = threadIdx.x, warp = tid >> 5, lane = tid & 31;
    int g = lane >> 2, tg = lane & 3;
    uint32_t sbase = smem_u32(sm);

    auto stage = [&](int t, int s) {
        int kv0 = t * 32;
        uint32_t base = sbase + s * 16384;
        #pragma unroll
        for (int i = 0; i < 4; i++) {  // K tile: 32 rows x 256B
            int op = i * 128 + tid;
            int r = op >> 4, c = op & 15;
            uint32_t dst = base + r * 256 + ((c ^ (r & 7)) << 4);
            const char* src = (const char*)g_kh + (size_t)(kv0 + r) * (HIDDEN * 2) + h * 256 + c * 16;
            CP16(dst, src);
        }
        #pragma unroll
        for (int i = 0; i < 4; i++) {  // V tile: 32 rows x 256B
            int op = i * 128 + tid;
            int r = op >> 4, c = op & 15;
            uint32_t dst = base + 8192 + r * 256 + ((c ^ (r & 7)) << 4);
            const char* src = (const char*)g_h + ((size_t)(kv0 + r) * NMOD + 2 * HIDDEN + h * HDIM) * 2 + c * 16;
            CP16(dst, src);
        }
        CP_COMMIT();
    };

    uint32_t qf[8][4];
    const uint32_t* qb = g_qh + (size_t)(q0 + warp * 16) * (HIDDEN / 2) + h * 64;
    #pragma unroll
    for (int ks = 0; ks < 8; ks++) {
        qf[ks][0] = qb[(size_t)g * (HIDDEN / 2) + ks * 8 + tg];
        qf[ks][1] = qb[(size_t)(g + 8) * (HIDDEN / 2) + ks * 8 + tg];
        qf[ks][2] = qb[(size_t)g * (HIDDEN / 2) + ks * 8 + tg + 4];
        qf[ks][3] = qb[(size_t)(g + 8) * (HIDDEN / 2) + ks * 8 + tg + 4];
    }

    float of[16][4];
    #pragma unroll
    for (int j = 0; j < 16; j++)
        #pragma unroll
        for (int v = 0; v < 4; v++) of[j][v] = 0.f;
    float l0 = 0.f, l1 = 0.f;

    stage(0, 0);
    stage(1, 1);

    for (int t = 0; t < LSEQ / 32; t++) {
        int st = t % 3;
        CP_WAIT1();
        __syncthreads();
        if (t + 2 < LSEQ / 32) stage(t + 2, (t + 2) % 3);
        else CP_COMMIT();

        uint32_t kbase = sbase + st * 16384;
        uint32_t vbase = kbase + 8192;

        float s_[4][4];
        #pragma unroll
        for (int j = 0; j < 4; j++)
            #pragma unroll
            for (int v = 0; v < 4; v++) s_[j][v] = 0.f;
        #pragma unroll
        for (int ks = 0; ks < 8; ks++) {
            #pragma unroll
            for (int hn = 0; hn < 2; hn++) {
                int r = hn * 16 + ((lane >> 4) << 3) + (lane & 7);
                int c = 2 * ks + ((lane >> 3) & 1);
                uint32_t ad = kbase + r * 256 + ((c ^ (r & 7)) << 4);
                uint32_t b0, b1, b2, b3;
                LDM_X4(b0, b1, b2, b3, ad);
                uint32_t bA[2] = {b0, b1}, bB[2] = {b2, b3};
                mma16(s_[2 * hn], qf[ks], bA);
                mma16(s_[2 * hn + 1], qf[ks], bB);
            }
        }

        #pragma unroll
        for (int j = 0; j < 4; j++) {
            s_[j][0] = __expf(s_[j][0] - SHIFT);
            s_[j][1] = __expf(s_[j][1] - SHIFT);
            s_[j][2] = __expf(s_[j][2] - SHIFT);
            s_[j][3] = __expf(s_[j][3] - SHIFT);
            l0 += s_[j][0] + s_[j][1];
            l1 += s_[j][2] + s_[j][3];
        }

        #pragma unroll
        for (int ks2 = 0; ks2 < 2; ks2++) {
            uint32_t af[4];
            af[0] = pk(s_[2 * ks2][0], s_[2 * ks2][1]);
            af[1] = pk(s_[2 * ks2][2], s_[2 * ks2][3]);
            af[2] = pk(s_[2 * ks2 + 1][0], s_[2 * ks2 + 1][1]);
            af[3] = pk(s_[2 * ks2 + 1][2], s_[2 * ks2 + 1][3]);
            #pragma unroll
            for (int tt = 0; tt < 8; tt++) {
                int r = ks2 * 16 + ((lane >> 3) & 1) * 8 + (lane & 7);
                int c = 2 * tt + (lane >> 4);
                uint32_t ad = vbase + r * 256 + ((c ^ (r & 7)) << 4);
                uint32_t b0, b1, b2, b3;
                LDM_X4T(b0, b1, b2, b3, ad);
                uint32_t bA[2] = {b0, b1}, bB[2] = {b2, b3};
                mma16(of[2 * tt], af, bA);
                mma16(of[2 * tt + 1], af, bB);
            }
        }
    }

    l0 += __shfl_xor_sync(~0u, l0, 1);
    l0 += __shfl_xor_sync(~0u, l0, 2);
    l1 += __shfl_xor_sync(~0u, l1, 1);
    l1 += __shfl_xor_sync(~0u, l1, 2);
    float il0 = 1.f / l0, il1 = 1.f / l1;
    int r0 = q0 + warp * 16 + g;
    int r1 = r0 + 8;
    #pragma unroll
    for (int j = 0; j < 16; j++) {
        int c = h * HDIM + j * 8 + 2 * tg;
        *(uint32_t*)&g_a2h[(size_t)r0 * NCAT + c] = pk(of[j][0] * il0, of[j][1] * il0);
        *(uint32_t*)&g_a2h[(size_t)r1 * NCAT + c] = pk(of[j][2] * il1, of[j][3] * il1);
    }
}

// ---------------- launch ----------------
extern "C" void kernel_launch(void* const* d_in, const int* in_sizes, int n_in,
                              void* d_out, int out_size) {
    const float* x     = (const float*)d_in[0];
    const float* vec   = (const float*)d_in[1];
    const float* pe    = (const float*)d_in[2];
    const float* w1    = (const float*)d_in[3];
    const float* b1    = (const float*)d_in[4];
    const float* w2    = (const float*)d_in[5];
    const float* b2    = (const float*)d_in[6];
    const float* mod_w = (const float*)d_in[7];
    const float* mod_b = (const float*)d_in[8];
    const float* qw    = (const float*)d_in[9];
    const float* kw    = (const float*)d_in[10];
    float* out = (float*)d_out;

    __half* w1h;  cudaGetSymbolAddress((void**)&w1h, g_w1h);
    __half* w2h;  cudaGetSymbolAddress((void**)&w2h, g_w2h);

    cudaFuncSetAttribute(gemm_cp<0>, cudaFuncAttributeMaxDynamicSharedMemorySize, 4 * 18432);
    cudaFuncSetAttribute(gemm_cp<1>, cudaFuncAttributeMaxDynamicSharedMemorySize, 4 * 13312);

    k_cvt<<<(HIDDEN * (N1 / 4)) / 256, 256>>>(w1, w1h);
    k_cvt<<<(NCAT * (HIDDEN / 4)) / 256, 256>>>(w2, w2h);
    k_mod<<<NMOD / 256, 256>>>(vec, mod_w, mod_b);
    k_ln<<<LSEQ, 256>>>(x);
    gemm_cp<0><<<dim3(16, 168), 256, 4 * 18432>>>(w1h, b1, nullptr, nullptr);
    k_qkrope<<<LSEQ, 256>>>(pe, qw, kw);
    k_attn<<<dim3(LSEQ / 64, NHEADS), 128>>>();
    gemm_cp<1><<<dim3(32, 24), 128, 4 * 13312>>>(w2h, b2, out, x);
}